// round 10
// baseline (speedup 1.0000x reference)
#include <cuda_runtime.h>
#include <cuda_fp16.h>
#include <stdint.h>
#include <math.h>

#define NTOK   257
#define BATCH  64
#define T_TOK  (BATCH * NTOK)   // 16448
#define DMODEL 1024
#define NHEAD  16
#define HD     64
#define HDIM   4096
#define LN_EPS 1e-5f
#define STRQ   3072              // fused qkv row stride

// ---------------- scratch (device globals; no allocations allowed) ----------
__device__ __align__(16) float g_qkv[(size_t)T_TOK * STRQ];
__device__ __align__(16) float g_att[(size_t)T_TOK * DMODEL];
__device__ __align__(16) float g_x1 [(size_t)T_TOK * DMODEL];
__device__ __align__(16) float g_h12[(size_t)T_TOK * 2 * HDIM];

__device__ __align__(16) __half g_a16[(size_t)T_TOK * DMODEL];
__device__ __align__(16) __half g_h16[(size_t)T_TOK * HDIM];
__device__ __align__(16) __half g_qkvw16[(size_t)3 * DMODEL * DMODEL];
__device__ __align__(16) __half g_pw16[(size_t)DMODEL * DMODEL];
__device__ __align__(16) __half g_w1216[(size_t)2 * HDIM * DMODEL];
__device__ __align__(16) __half g_w316[(size_t)DMODEL * HDIM];
__device__ __align__(16) float  g_qkvb[3 * DMODEL];
__device__ __align__(16) float  g_w12b[2 * HDIM];

// ---------------- fp32 -> fp16 helpers --------------------------------------
__device__ __forceinline__ uint2 pack16(float4 t)
{
    __half2 a = __floats2half2_rn(t.x, t.y);
    __half2 b = __floats2half2_rn(t.z, t.w);
    uint2 r;
    r.x = *(uint32_t*)&a;
    r.y = *(uint32_t*)&b;
    return r;
}

// one launch converts up to 4 weight matrices (blockIdx.y selects)
__global__ void __launch_bounds__(256) cvt4(const float* __restrict__ s0, __half* __restrict__ d0,
                                            const float* __restrict__ s1, __half* __restrict__ d1,
                                            const float* __restrict__ s2, __half* __restrict__ d2,
                                            const float* __restrict__ s3, __half* __restrict__ d3,
                                            int n4)
{
    int i = blockIdx.x * 256 + threadIdx.x;
    if (i >= n4) return;
    const float* s = (blockIdx.y == 0) ? s0 : (blockIdx.y == 1) ? s1 : (blockIdx.y == 2) ? s2 : s3;
    __half*      d = (blockIdx.y == 0) ? d0 : (blockIdx.y == 1) ? d1 : (blockIdx.y == 2) ? d2 : d3;
    ((uint2*)d)[i] = pack16(((const float4*)s)[i]);
}

__global__ void __launch_bounds__(256) pack_biases(const float* __restrict__ qb,
                                                   const float* __restrict__ vb,
                                                   const float* __restrict__ b1,
                                                   const float* __restrict__ b2,
                                                   float* __restrict__ qkvb,
                                                   float* __restrict__ w12b)
{
    int i = blockIdx.x * 256 + threadIdx.x;
    if (i < 3 * DMODEL) {
        qkvb[i] = (i < DMODEL) ? qb[i] : ((i < 2 * DMODEL) ? 0.f : vb[i - 2 * DMODEL]);
    } else {
        int j = i - 3 * DMODEL;
        if (j < 2 * HDIM) w12b[j] = (j < HDIM) ? b1[j] : b2[j - HDIM];
    }
}

// ---------------- mma.sync GEMM: C = A*B^T (+bias)(+res), fp32 out ----------
// CTA tile 128x256, 8 warps (2x4), warp tile 64x64, K chunk 32, 3-stage pipe.
#define RSB    80                 // smem row stride bytes (40 halves)
#define APLANE (128 * RSB)        // 10240
#define BPLANE (256 * RSB)        // 20480
#define STAGE  (APLANE + BPLANE)  // 30720
#define NSTAGE 3
#define SMEM_G (NSTAGE * STAGE)   // 92160

#define LDSM4(r0, r1, r2, r3, addr) \
    asm volatile("ldmatrix.sync.aligned.m8n8.x4.shared.b16 {%0,%1,%2,%3}, [%4];" \
                 : "=r"(r0), "=r"(r1), "=r"(r2), "=r"(r3) : "r"(addr))

#define MMA16816(c, a, b) \
    asm volatile("mma.sync.aligned.m16n8k16.row.col.f32.f16.f16.f32 " \
                 "{%0,%1,%2,%3}, {%4,%5,%6,%7}, {%8,%9}, {%0,%1,%2,%3};" \
                 : "+f"((c)[0]), "+f"((c)[1]), "+f"((c)[2]), "+f"((c)[3]) \
                 : "r"((a)[0]), "r"((a)[1]), "r"((a)[2]), "r"((a)[3]), \
                   "r"((b)[0]), "r"((b)[1]))

template<bool RES>
__global__ void __launch_bounds__(256) tgemm(const __half* __restrict__ A,
                                             const __half* __restrict__ B,
                                             const float* __restrict__ bias,
                                             const float* __restrict__ res,
                                             float* __restrict__ C,
                                             int M, int N, int K)
{
    extern __shared__ __align__(16) char dsm[];
    uint32_t sb = (uint32_t)__cvta_generic_to_shared(dsm);

    int tid = threadIdx.x, lane = tid & 31, warp = tid >> 5;
    int wm = warp >> 2, wn = warp & 3;           // warp grid 2 x 4
    int m0 = blockIdx.y * 128, n0 = blockIdx.x * 256;

    float acc[4][8][4];
#pragma unroll
    for (int i = 0; i < 4; i++)
#pragma unroll
        for (int j = 0; j < 8; j++)
#pragma unroll
            for (int r = 0; r < 4; r++) acc[i][j][r] = 0.f;

    auto issue_loads = [&](int c) {
        int k0 = c * 32;
        uint32_t sbuf = sb + (uint32_t)(c % NSTAGE) * STAGE;
#pragma unroll
        for (int i = 0; i < 6; i++) {
            int gi = i * 256 + tid;       // 0..1535
            if (gi < 512) {               // A plane: 128 rows x 4 chunks
                int row = gi >> 2, cc = gi & 3;
                int grow = m0 + row;
                int sz = 16;
                if (grow >= M) { grow = 0; sz = 0; }
                const void* src = A + (size_t)grow * K + k0 + cc * 8;
                uint32_t dst = sbuf + (uint32_t)(row * RSB + cc * 16);
                asm volatile("cp.async.ca.shared.global [%0], [%1], 16, %2;"
                             :: "r"(dst), "l"(src), "r"(sz));
            } else {                      // B plane: 256 rows x 4 chunks
                int idx = gi - 512;
                int row = idx >> 2, cc = idx & 3;
                const void* src = B + (size_t)(n0 + row) * K + k0 + cc * 8;
                uint32_t dst = sbuf + APLANE + (uint32_t)(row * RSB + cc * 16);
                asm volatile("cp.async.cg.shared.global [%0], [%1], 16;"
                             :: "r"(dst), "l"(src));
            }
        }
        asm volatile("cp.async.commit_group;" ::: "memory");
    };

    int KT = K >> 5;
    issue_loads(0);
    issue_loads(1);

    for (int c = 0; c < KT; c++) {
        if (c + 1 < KT) {
            asm volatile("cp.async.wait_group 1;" ::: "memory");
        } else {
            asm volatile("cp.async.wait_group 0;" ::: "memory");
        }
        __syncthreads();
        if (c + 2 < KT) issue_loads(c + 2);

        uint32_t sbuf = sb + (uint32_t)(c % NSTAGE) * STAGE;
#pragma unroll
        for (int kk = 0; kk < 32; kk += 16) {
            uint32_t af[4][4], bf[8][2];
#pragma unroll
            for (int mi = 0; mi < 4; mi++) {
                int arow = wm * 64 + mi * 16 + (lane & 15);
                uint32_t aoff = (uint32_t)(arow * RSB + (kk + (lane >> 4) * 8) * 2);
                LDSM4(af[mi][0], af[mi][1], af[mi][2], af[mi][3], sbuf + aoff);
            }
#pragma unroll
            for (int nj = 0; nj < 4; nj++) {
                int g = lane >> 3;
                int nrow = wn * 64 + nj * 16 + (g >> 1) * 8 + (lane & 7);
                uint32_t boff = (uint32_t)(nrow * RSB + (kk + (g & 1) * 8) * 2);
                LDSM4(bf[nj*2][0], bf[nj*2][1], bf[nj*2+1][0], bf[nj*2+1][1],
                      sbuf + APLANE + boff);
            }
#pragma unroll
            for (int mi = 0; mi < 4; mi++)
#pragma unroll
                for (int ni = 0; ni < 8; ni++)
                    MMA16816(acc[mi][ni], af[mi], bf[ni]);
        }
    }

    __syncthreads();
    // epilogue
#pragma unroll
    for (int mi = 0; mi < 4; mi++) {
#pragma unroll
        for (int ni = 0; ni < 8; ni++) {
            int r0 = m0 + wm * 64 + mi * 16 + (lane >> 2);
            int col = n0 + wn * 64 + ni * 8 + (lane & 3) * 2;
            float bx = 0.f, by = 0.f;
            if (bias) { bx = bias[col]; by = bias[col + 1]; }
            float2 v0, v1;
            v0.x = acc[mi][ni][0] + bx; v0.y = acc[mi][ni][1] + by;
            v1.x = acc[mi][ni][2] + bx; v1.y = acc[mi][ni][3] + by;
            if (r0 < M) {
                size_t off = (size_t)r0 * N + col;
                if (RES) { float2 rr = *(const float2*)&res[off]; v0.x += rr.x; v0.y += rr.y; }
                *(float2*)&C[off] = v0;
            }
            if (r0 + 8 < M) {
                size_t off = (size_t)(r0 + 8) * N + col;
                if (RES) { float2 rr = *(const float2*)&res[off]; v1.x += rr.x; v1.y += rr.y; }
                *(float2*)&C[off] = v1;
            }
        }
    }
}

// ---------------- LayerNorm -> fp16 plane ------------------------------------
template<int W>
__global__ void __launch_bounds__(256) ln16(const float* __restrict__ x,
                                            const float* __restrict__ g,
                                            const float* __restrict__ b,
                                            __half* __restrict__ o16)
{
    constexpr int V = W / 1024;
    __shared__ float red0[8], red1[8];
    __shared__ float stats[2];
    size_t rb = (size_t)blockIdx.x * W;
    const float4* xr = (const float4*)(x + rb);
    float4 vv[V];
    float s = 0.f, s2 = 0.f;
#pragma unroll
    for (int i = 0; i < V; i++) {
        float4 t = xr[threadIdx.x + i * 256];
        vv[i] = t;
        s  += t.x + t.y + t.z + t.w;
        s2 += t.x*t.x + t.y*t.y + t.z*t.z + t.w*t.w;
    }
#pragma unroll
    for (int o = 16; o; o >>= 1) {
        s  += __shfl_xor_sync(0xffffffffu, s,  o);
        s2 += __shfl_xor_sync(0xffffffffu, s2, o);
    }
    if ((threadIdx.x & 31) == 0) { red0[threadIdx.x >> 5] = s; red1[threadIdx.x >> 5] = s2; }
    __syncthreads();
    if (threadIdx.x == 0) {
        float a = 0.f, c = 0.f;
#pragma unroll
        for (int i = 0; i < 8; i++) { a += red0[i]; c += red1[i]; }
        float mu  = a / (float)W;
        float var = c / (float)W - mu * mu;
        stats[0] = mu;
        stats[1] = rsqrtf(var + LN_EPS);
    }
    __syncthreads();
    float mu = stats[0], inv = stats[1];
    const float4* g4 = (const float4*)g;
    const float4* b4 = (const float4*)b;
#pragma unroll
    for (int i = 0; i < V; i++) {
        int c = threadIdx.x + i * 256;
        float4 gg = g4[c], bb = b4[c], t = vv[i], o;
        o.x = (t.x - mu) * inv * gg.x + bb.x;
        o.y = (t.y - mu) * inv * gg.y + bb.y;
        o.z = (t.z - mu) * inv * gg.z + bb.z;
        o.w = (t.w - mu) * inv * gg.w + bb.w;
        ((uint2*)(o16 + rb))[c] = pack16(o);
    }
}

// ---------------- fused SiLU(x1)*x2 -> LayerNorm -> fp16 (from fused h12) ---
__global__ void __launch_bounds__(256) silu_ln16(const float* __restrict__ h12,
                                                 const float* __restrict__ g,
                                                 const float* __restrict__ b,
                                                 __half* __restrict__ o16)
{
    constexpr int W = HDIM;
    constexpr int V = W / 1024;
    __shared__ float red0[8], red1[8];
    __shared__ float stats[2];
    size_t rb12 = (size_t)blockIdx.x * (2 * HDIM);
    size_t rb   = (size_t)blockIdx.x * W;
    const float4* ar = (const float4*)(h12 + rb12);
    const float4* cr = (const float4*)(h12 + rb12 + HDIM);
    float4 vv[V];
    float s = 0.f, s2 = 0.f;
#pragma unroll
    for (int i = 0; i < V; i++) {
        float4 a = ar[threadIdx.x + i * 256];
        float4 c = cr[threadIdx.x + i * 256];
        float4 t;
        t.x = a.x / (1.f + __expf(-a.x)) * c.x;
        t.y = a.y / (1.f + __expf(-a.y)) * c.y;
        t.z = a.z / (1.f + __expf(-a.z)) * c.z;
        t.w = a.w / (1.f + __expf(-a.w)) * c.w;
        vv[i] = t;
        s  += t.x + t.y + t.z + t.w;
        s2 += t.x*t.x + t.y*t.y + t.z*t.z + t.w*t.w;
    }
#pragma unroll
    for (int o = 16; o; o >>= 1) {
        s  += __shfl_xor_sync(0xffffffffu, s,  o);
        s2 += __shfl_xor_sync(0xffffffffu, s2, o);
    }
    if ((threadIdx.x & 31) == 0) { red0[threadIdx.x >> 5] = s; red1[threadIdx.x >> 5] = s2; }
    __syncthreads();
    if (threadIdx.x == 0) {
        float a = 0.f, c = 0.f;
#pragma unroll
        for (int i = 0; i < 8; i++) { a += red0[i]; c += red1[i]; }
        float mu  = a / (float)W;
        float var = c / (float)W - mu * mu;
        stats[0] = mu;
        stats[1] = rsqrtf(var + LN_EPS);
    }
    __syncthreads();
    float mu = stats[0], inv = stats[1];
    const float4* g4 = (const float4*)g;
    const float4* b4 = (const float4*)b;
#pragma unroll
    for (int i = 0; i < V; i++) {
        int c = threadIdx.x + i * 256;
        float4 gg = g4[c], bb = b4[c], t = vv[i], o;
        o.x = (t.x - mu) * inv * gg.x + bb.x;
        o.y = (t.y - mu) * inv * gg.y + bb.y;
        o.z = (t.z - mu) * inv * gg.z + bb.z;
        o.w = (t.w - mu) * inv * gg.w + bb.w;
        ((uint2*)(o16 + rb))[c] = pack16(o);
    }
}

// ---------------- RoPE on q,k in fused qkv buffer; scale q ------------------
__global__ void __launch_bounds__(256) rope_kernel(float* __restrict__ qkv,
                                                   const float* __restrict__ cosb,
                                                   const float* __restrict__ sinb)
{
    const float scale = 0.125f;
    int row = blockIdx.x;
    int n = row % NTOK;
    float4* qr = (float4*)(qkv + (size_t)row * STRQ);
    float4* kr = (float4*)(qkv + (size_t)row * STRQ + DMODEL);
    int ci = threadIdx.x;
    if (n == 0) {
        float4 t = qr[ci];
        t.x *= scale; t.y *= scale; t.z *= scale; t.w *= scale;
        qr[ci] = t;
        return;
    }
    int d = (ci * 4) & 63;
    const float4 cs = *(const float4*)(cosb + (size_t)(n - 1) * HD + d);
    const float4 sn = *(const float4*)(sinb + (size_t)(n - 1) * HD + d);
    float4 t = qr[ci], o;
    o.x = t.x * cs.x - t.y * sn.x;
    o.y = t.y * cs.y + t.x * sn.y;
    o.z = t.z * cs.z - t.w * sn.z;
    o.w = t.w * cs.w + t.z * sn.w;
    o.x *= scale; o.y *= scale; o.z *= scale; o.w *= scale;
    qr[ci] = o;
    t = kr[ci];
    o.x = t.x * cs.x - t.y * sn.x;
    o.y = t.y * cs.y + t.x * sn.y;
    o.z = t.z * cs.z - t.w * sn.z;
    o.w = t.w * cs.w + t.z * sn.w;
    kr[ci] = o;
}

// ---------------- attention v3: contiguous-key ownership --------------------
// KsTm[d][j] = K[j+1][d] (keys 1..256), k0[d] = K[0][d].
// Thread `lane` owns keys j = lane*8 .. lane*8+7 (i.e. kk = j+1).
// Explicit float-offset layout; psH padded to 16B alignment.
#define OFF_KSTM 0
#define OFF_K0   (OFF_KSTM + 64 * 264)         // 16896
#define OFF_VS   (OFF_K0 + 64)                 // 16960
#define OFF_BS   (OFF_VS + 257 * 65)           // 33665
#define OFF_QS   (OFF_BS + 964)                // 34629
#define OFF_P0   (OFF_QS + 8 * 8 * 64)         // 38725
#define OFF_PSH  ((OFF_P0 + 64 + 3) & ~3)      // 38792 (16B aligned)
#define ATTN_SMEM_BYTES (OFF_PSH * 4 + 8 * 8 * 264 * 2)   // 188960

#define KTM_STR 264

__global__ void __launch_bounds__(256) attn_kernel(const float* __restrict__ qkv,
                                                   const float* __restrict__ table,
                                                   float* __restrict__ out)
{
    extern __shared__ __align__(16) float sm[];
    float* KsTm = sm + OFF_KSTM;           // [64][264]
    float* k0   = sm + OFF_K0;             // [64]
    float* Vs   = sm + OFF_VS;             // [257][65]
    float* bs   = sm + OFF_BS;             // [964]
    float* qs   = sm + OFF_QS;             // [8w][8][64]
    float* p0s  = sm + OFF_P0;             // [8w][8]
    __half* psH = (__half*)(sm + OFF_PSH); // [8w][8][264] halves, 16B aligned

    int bh = blockIdx.x;
    int b = bh >> 4, h = bh & 15;
    int tid = threadIdx.x, lane = tid & 31, w = tid >> 5;
    const float* qg = qkv + (size_t)b * NTOK * STRQ + h * HD;
    const float* kg = qg + DMODEL;
    const float* vg = qg + 2 * DMODEL;

    for (int i = tid; i < NTOK * HD; i += 256) {
        int r = i >> 6, c = i & 63;
        float kv = kg[(size_t)r * STRQ + c];
        Vs[r * 65 + c] = vg[(size_t)r * STRQ + c];
        if (r == 0) k0[c] = kv;
        else        KsTm[c * KTM_STR + (r - 1)] = kv;
    }
    for (int i = tid; i < 964; i += 256) bs[i] = table[(size_t)i * NHEAD + h];
    __syncthreads();

    float* qsw = qs + w * 8 * 64;
    float* p0w = p0s + w * 8;
    __half* psw = psH + w * 8 * 264;

    for (int qb = w * 8; qb < NTOK; qb += 64) {
#pragma unroll
        for (int a = 0; a < 8; a++) {
            int qi = qb + a;
            float v0 = 0.f, v1 = 0.f;
            if (qi < NTOK) {
                v0 = qg[(size_t)qi * STRQ + lane];
                v1 = qg[(size_t)qi * STRQ + lane + 32];
            }
            qsw[a * 64 + lane]      = v0;
            qsw[a * 64 + lane + 32] = v1;
        }
        __syncwarp();

        // QK^T for owned keys + CLS key
        float e[8][8], e0[8];
#pragma unroll
        for (int a = 0; a < 8; a++) {
            e0[a] = 0.f;
#pragma unroll
            for (int i = 0; i < 8; i++) e[a][i] = 0.f;
        }
        for (int d = 0; d < 64; d++) {
            float4 ka = *(float4*)&KsTm[d * KTM_STR + lane * 8];
            float4 kb = *(float4*)&KsTm[d * KTM_STR + lane * 8 + 4];
            float kz = k0[d];
#pragma unroll
            for (int a = 0; a < 8; a++) {
                float qv = qsw[a * 64 + d];
                e[a][0] += qv * ka.x; e[a][1] += qv * ka.y;
                e[a][2] += qv * ka.z; e[a][3] += qv * ka.w;
                e[a][4] += qv * kb.x; e[a][5] += qv * kb.y;
                e[a][6] += qv * kb.z; e[a][7] += qv * kb.w;
                e0[a]   += qv * kz;
            }
        }

        // softmax per q-row; write P fp16 (cols shifted: col j = key j+1)
#pragma unroll
        for (int a = 0; a < 8; a++) {
            int qi = qb + a;
            bool q0 = (qi == 0);
            int pq = qi - 1, chq = pq >> 4, cwq = pq & 15;
            float ee[8];
#pragma unroll
            for (int i = 0; i < 8; i++) {
                int pk = lane * 8 + i;
                int idx = q0 ? 961
                             : (chq - (pk >> 4) + 15) * 31 + (cwq - (pk & 15) + 15);
                ee[i] = e[a][i] + bs[idx];
            }
            float e0b = e0[a] + bs[q0 ? 963 : 962];
            float mx = e0b;
#pragma unroll
            for (int i = 0; i < 8; i++) mx = fmaxf(mx, ee[i]);
#pragma unroll
            for (int o = 16; o; o >>= 1) mx = fmaxf(mx, __shfl_xor_sync(0xffffffffu, mx, o));
            float p0v = __expf(e0b - mx);
            float sum = (lane == 0) ? p0v : 0.f;
#pragma unroll
            for (int i = 0; i < 8; i++) { ee[i] = __expf(ee[i] - mx); sum += ee[i]; }
#pragma unroll
            for (int o = 16; o; o >>= 1) sum += __shfl_xor_sync(0xffffffffu, sum, o);
            float inv = 1.f / sum;
            __half2 h0 = __floats2half2_rn(ee[0] * inv, ee[1] * inv);
            __half2 h1 = __floats2half2_rn(ee[2] * inv, ee[3] * inv);
            __half2 h2 = __floats2half2_rn(ee[4] * inv, ee[5] * inv);
            __half2 h3 = __floats2half2_rn(ee[6] * inv, ee[7] * inv);
            uint4 pk4;
            pk4.x = *(uint32_t*)&h0; pk4.y = *(uint32_t*)&h1;
            pk4.z = *(uint32_t*)&h2; pk4.w = *(uint32_t*)&h3;
            *(uint4*)&psw[a * 264 + lane * 8] = pk4;
            if (lane == 0) p0w[a] = p0v * inv;
        }
        __syncwarp();

        // AV: keys 1..256 via psw cols 0..255, then CLS key
        float av[8][2];
#pragma unroll
        for (int a = 0; a < 8; a++) { av[a][0] = 0.f; av[a][1] = 0.f; }

        for (int jq = 0; jq < 64; jq++) {
            int j = jq * 4;
            float v00 = Vs[(j + 1) * 65 + lane], v01 = Vs[(j + 1) * 65 + lane + 32];
            float v10 = Vs[(j + 2) * 65 + lane], v11 = Vs[(j + 2) * 65 + lane + 32];
            float v20 = Vs[(j + 3) * 65 + lane], v21 = Vs[(j + 3) * 65 + lane + 32];
            float v30 = Vs[(j + 4) * 65 + lane], v31 = Vs[(j + 4) * 65 + lane + 32];
#pragma unroll
            for (int a = 0; a < 8; a++) {
                uint2 praw = *(uint2*)&psw[a * 264 + j];
                float2 f01 = __half22float2(*(__half2*)&praw.x);
                float2 f23 = __half22float2(*(__half2*)&praw.y);
                av[a][0] += f01.x * v00 + f01.y * v10 + f23.x * v20 + f23.y * v30;
                av[a][1] += f01.x * v01 + f01.y * v11 + f23.x * v21 + f23.y * v31;
            }
        }
        {
            float vz0 = Vs[lane], vz1 = Vs[lane + 32];
#pragma unroll
            for (int a = 0; a < 8; a++) {
                float p0v = p0w[a];
                av[a][0] += p0v * vz0;
                av[a][1] += p0v * vz1;
            }
        }
#pragma unroll
        for (int a = 0; a < 8; a++) {
            int qi = qb + a;
            if (qi < NTOK) {
                size_t off = ((size_t)b * NTOK + qi) * DMODEL + h * HD;
                out[off + lane]      = av[a][0];
                out[off + lane + 32] = av[a][1];
            }
        }
        __syncwarp();
    }
}

// ---------------- launch -----------------------------------------------------
extern "C" void kernel_launch(void* const* d_in, const int* in_sizes, int n_in,
                              void* d_out, int out_size)
{
    const float* x        = (const float*)d_in[0];
    const float* rope_cos = (const float*)d_in[1];
    const float* rope_sin = (const float*)d_in[2];
    const float* q_w      = (const float*)d_in[3];
    const float* q_b      = (const float*)d_in[4];
    const float* k_w      = (const float*)d_in[5];
    const float* v_w      = (const float*)d_in[6];
    const float* v_b      = (const float*)d_in[7];
    const float* table    = (const float*)d_in[8];
    const float* in_g     = (const float*)d_in[9];
    const float* in_b     = (const float*)d_in[10];
    const float* proj_w   = (const float*)d_in[11];
    const float* proj_b   = (const float*)d_in[12];
    const float* n1g      = (const float*)d_in[13];
    const float* n1b      = (const float*)d_in[14];
    const float* n2g      = (const float*)d_in[15];
    const float* n2b      = (const float*)d_in[16];
    const float* w1       = (const float*)d_in[17];
    const float* w1b      = (const float*)d_in[18];
    const float* w2       = (const float*)d_in[19];
    const float* w2b      = (const float*)d_in[20];
    const float* fg       = (const float*)d_in[21];
    const float* fb       = (const float*)d_in[22];
    const float* w3       = (const float*)d_in[23];
    const float* w3b      = (const float*)d_in[24];
    float* out = (float*)d_out;

    float *qkv, *att, *x1, *h12, *qkvb, *w12b;
    __half *a16, *h16, *qkvw16, *pw16, *w1216, *w316;
    cudaGetSymbolAddress((void**)&qkv,    g_qkv);
    cudaGetSymbolAddress((void**)&att,    g_att);
    cudaGetSymbolAddress((void**)&x1,     g_x1);
    cudaGetSymbolAddress((void**)&h12,    g_h12);
    cudaGetSymbolAddress((void**)&a16,    g_a16);
    cudaGetSymbolAddress((void**)&h16,    g_h16);
    cudaGetSymbolAddress((void**)&qkvw16, g_qkvw16);
    cudaGetSymbolAddress((void**)&pw16,   g_pw16);
    cudaGetSymbolAddress((void**)&w1216,  g_w1216);
    cudaGetSymbolAddress((void**)&w316,   g_w316);
    cudaGetSymbolAddress((void**)&qkvb,   g_qkvb);
    cudaGetSymbolAddress((void**)&w12b,   g_w12b);

    cudaFuncSetAttribute(attn_kernel, cudaFuncAttributeMaxDynamicSharedMemorySize, ATTN_SMEM_BYTES);
    cudaFuncSetAttribute(tgemm<false>, cudaFuncAttributeMaxDynamicSharedMemorySize, SMEM_G);
    cudaFuncSetAttribute(tgemm<true>,  cudaFuncAttributeMaxDynamicSharedMemorySize, SMEM_G);

    dim3 blk(256);
    dim3 gQKV(3 * DMODEL / 256, (T_TOK + 127) / 128);   // (12, 129)
    dim3 gP(DMODEL / 256,       (T_TOK + 127) / 128);   // (4, 129)
    dim3 gW12(2 * HDIM / 256,   (T_TOK + 127) / 128);   // (32, 129)

    const int n4_1M = DMODEL * DMODEL / 4;    // 262144
    const int n4_4M = HDIM * DMODEL / 4;      // 1048576

    // #1: convert q/k/v/proj weights
    cvt4<<<dim3((n4_1M + 255) / 256, 4), blk>>>(
        q_w, qkvw16,
        k_w, qkvw16 + (size_t)DMODEL * DMODEL,
        v_w, qkvw16 + (size_t)2 * DMODEL * DMODEL,
        proj_w, pw16, n4_1M);
    // #2: pack biases
    pack_biases<<<(3 * DMODEL + 2 * HDIM + 255) / 256, blk>>>(q_b, v_b, w1b, w2b, qkvb, w12b);
    // #3: norm1 -> fp16
    ln16<DMODEL><<<T_TOK, blk>>>(x, n1g, n1b, a16);
    // #4: fused QKV projection
    tgemm<false><<<gQKV, blk, SMEM_G>>>(a16, qkvw16, qkvb, nullptr, qkv, T_TOK, 3 * DMODEL, DMODEL);
    // #5: RoPE + q scaling
    rope_kernel<<<T_TOK, blk>>>(qkv, rope_cos, rope_sin);
    // #6: attention  (ncu -s 5 -c 1 profiles this launch)
    attn_kernel<<<BATCH * NHEAD, blk, ATTN_SMEM_BYTES>>>(qkv, table, att);
    // #7: convert FFN weights (needed only from launch #11 on)
    cvt4<<<dim3((n4_4M + 255) / 256, 3), blk>>>(
        w1, w1216,
        w2, w1216 + (size_t)HDIM * DMODEL,
        w3, w316,
        w3, w316, n4_4M);
    // #8: inner LN -> fp16
    ln16<DMODEL><<<T_TOK, blk>>>(att, in_g, in_b, a16);
    // #9: proj (+ residual with x) -> x1
    tgemm<true><<<gP, blk, SMEM_G>>>(a16, pw16, proj_b, x, x1, T_TOK, DMODEL, DMODEL);
    // #10: norm2 -> fp16
    ln16<DMODEL><<<T_TOK, blk>>>(x1, n2g, n2b, a16);
    // #11: fused FFN up projection (w1|w2)
    tgemm<false><<<gW12, blk, SMEM_G>>>(a16, w1216, w12b, nullptr, h12, T_TOK, 2 * HDIM, DMODEL);
    // #12: silu(x1h)*x2h -> ffn LN -> fp16
    silu_ln16<<<T_TOK, blk>>>(h12, fg, fb, h16);
    // #13: down projection + residual -> out
    tgemm<true><<<gP, blk, SMEM_G>>>(h16, w316, w3b, x1, out, T_TOK, DMODEL, HDIM);
}

// round 11
// speedup vs baseline: 1.0270x; 1.0270x over previous
#include <cuda_runtime.h>
#include <cuda_fp16.h>
#include <stdint.h>
#include <math.h>

#define NTOK   257
#define BATCH  64
#define T_TOK  (BATCH * NTOK)   // 16448
#define DMODEL 1024
#define NHEAD  16
#define HD     64
#define HDIM   4096
#define LN_EPS 1e-5f
#define STRQ   3072              // fused qkv row stride

// ---------------- scratch (device globals; no allocations allowed) ----------
__device__ __align__(16) float g_qkv[(size_t)T_TOK * STRQ];
__device__ __align__(16) float g_att[(size_t)T_TOK * DMODEL];
__device__ __align__(16) float g_x1 [(size_t)T_TOK * DMODEL];
__device__ __align__(16) float g_h12[(size_t)T_TOK * 2 * HDIM];

__device__ __align__(16) __half g_a16[(size_t)T_TOK * DMODEL];
__device__ __align__(16) __half g_h16[(size_t)T_TOK * HDIM];
__device__ __align__(16) __half g_qkvw16[(size_t)3 * DMODEL * DMODEL];
__device__ __align__(16) __half g_pw16[(size_t)DMODEL * DMODEL];
__device__ __align__(16) __half g_w1216[(size_t)2 * HDIM * DMODEL];
__device__ __align__(16) __half g_w316[(size_t)DMODEL * HDIM];
__device__ __align__(16) float  g_qkvb[3 * DMODEL];
__device__ __align__(16) float  g_w12b[2 * HDIM];

// ---------------- fp32 -> fp16 helpers --------------------------------------
__device__ __forceinline__ uint2 pack16(float4 t)
{
    __half2 a = __floats2half2_rn(t.x, t.y);
    __half2 b = __floats2half2_rn(t.z, t.w);
    uint2 r;
    r.x = *(uint32_t*)&a;
    r.y = *(uint32_t*)&b;
    return r;
}

// one launch converts up to 4 weight matrices (blockIdx.y selects)
__global__ void __launch_bounds__(256) cvt4(const float* __restrict__ s0, __half* __restrict__ d0,
                                            const float* __restrict__ s1, __half* __restrict__ d1,
                                            const float* __restrict__ s2, __half* __restrict__ d2,
                                            const float* __restrict__ s3, __half* __restrict__ d3,
                                            int n4)
{
    int i = blockIdx.x * 256 + threadIdx.x;
    if (i >= n4) return;
    const float* s = (blockIdx.y == 0) ? s0 : (blockIdx.y == 1) ? s1 : (blockIdx.y == 2) ? s2 : s3;
    __half*      d = (blockIdx.y == 0) ? d0 : (blockIdx.y == 1) ? d1 : (blockIdx.y == 2) ? d2 : d3;
    ((uint2*)d)[i] = pack16(((const float4*)s)[i]);
}

__global__ void __launch_bounds__(256) pack_biases(const float* __restrict__ qb,
                                                   const float* __restrict__ vb,
                                                   const float* __restrict__ b1,
                                                   const float* __restrict__ b2,
                                                   float* __restrict__ qkvb,
                                                   float* __restrict__ w12b)
{
    int i = blockIdx.x * 256 + threadIdx.x;
    if (i < 3 * DMODEL) {
        qkvb[i] = (i < DMODEL) ? qb[i] : ((i < 2 * DMODEL) ? 0.f : vb[i - 2 * DMODEL]);
    } else {
        int j = i - 3 * DMODEL;
        if (j < 2 * HDIM) w12b[j] = (j < HDIM) ? b1[j] : b2[j - HDIM];
    }
}

// ---------------- mma.sync GEMM: C = A*B^T (+bias)(+res), fp32 out ----------
// CTA tile 128x256, 8 warps (2x4), warp tile 64x64, K chunk 32, 3-stage
// cp.async pipeline + register double-buffered fragments.
#define RSB    80                 // smem row stride bytes (40 halves)
#define APLANE (128 * RSB)        // 10240
#define BPLANE (256 * RSB)        // 20480
#define STAGE  (APLANE + BPLANE)  // 30720
#define NSTAGE 3
#define SMEM_G (NSTAGE * STAGE)   // 92160

#define LDSM4(r0, r1, r2, r3, addr) \
    asm volatile("ldmatrix.sync.aligned.m8n8.x4.shared.b16 {%0,%1,%2,%3}, [%4];" \
                 : "=r"(r0), "=r"(r1), "=r"(r2), "=r"(r3) : "r"(addr))

#define MMA16816(c, a, b) \
    asm volatile("mma.sync.aligned.m16n8k16.row.col.f32.f16.f16.f32 " \
                 "{%0,%1,%2,%3}, {%4,%5,%6,%7}, {%8,%9}, {%0,%1,%2,%3};" \
                 : "+f"((c)[0]), "+f"((c)[1]), "+f"((c)[2]), "+f"((c)[3]) \
                 : "r"((a)[0]), "r"((a)[1]), "r"((a)[2]), "r"((a)[3]), \
                   "r"((b)[0]), "r"((b)[1]))

// fragment load: af[4][4], bf[8][2] for one kk (0 or 16) from stage buffer
#define LOAD_FRAGS(sbuf, kk, af, bf) do {                                          \
    _Pragma("unroll")                                                              \
    for (int mi = 0; mi < 4; mi++) {                                               \
        int arow = wm * 64 + mi * 16 + (lane & 15);                                \
        uint32_t aoff = (uint32_t)(arow * RSB + ((kk) + (lane >> 4) * 8) * 2);     \
        LDSM4(af[mi][0], af[mi][1], af[mi][2], af[mi][3], (sbuf) + aoff);          \
    }                                                                              \
    _Pragma("unroll")                                                              \
    for (int nj = 0; nj < 4; nj++) {                                               \
        int g = lane >> 3;                                                         \
        int nrow = wn * 64 + nj * 16 + (g >> 1) * 8 + (lane & 7);                  \
        uint32_t boff = (uint32_t)(nrow * RSB + ((kk) + (g & 1) * 8) * 2);         \
        LDSM4(bf[nj*2][0], bf[nj*2][1], bf[nj*2+1][0], bf[nj*2+1][1],              \
              (sbuf) + APLANE + boff);                                             \
    }                                                                              \
} while (0)

#define MMA_TILE(af, bf) do {                                                      \
    _Pragma("unroll")                                                              \
    for (int mi = 0; mi < 4; mi++)                                                 \
        _Pragma("unroll")                                                          \
        for (int ni = 0; ni < 8; ni++)                                             \
            MMA16816(acc[mi][ni], af[mi], bf[ni]);                                 \
} while (0)

template<bool RES>
__global__ void __launch_bounds__(256) tgemm(const __half* __restrict__ A,
                                             const __half* __restrict__ B,
                                             const float* __restrict__ bias,
                                             const float* __restrict__ res,
                                             float* __restrict__ C,
                                             int M, int N, int K)
{
    extern __shared__ __align__(16) char dsm[];
    uint32_t sb = (uint32_t)__cvta_generic_to_shared(dsm);

    int tid = threadIdx.x, lane = tid & 31, warp = tid >> 5;
    int wm = warp >> 2, wn = warp & 3;           // warp grid 2 x 4
    int m0 = blockIdx.y * 128, n0 = blockIdx.x * 256;

    float acc[4][8][4];
#pragma unroll
    for (int i = 0; i < 4; i++)
#pragma unroll
        for (int j = 0; j < 8; j++)
#pragma unroll
            for (int r = 0; r < 4; r++) acc[i][j][r] = 0.f;

    auto issue_loads = [&](int c) {
        int k0 = c * 32;
        uint32_t sbuf = sb + (uint32_t)(c % NSTAGE) * STAGE;
#pragma unroll
        for (int i = 0; i < 6; i++) {
            int gi = i * 256 + tid;       // 0..1535
            if (gi < 512) {               // A plane: 128 rows x 4 chunks
                int row = gi >> 2, cc = gi & 3;
                int grow = m0 + row;
                int sz = 16;
                if (grow >= M) { grow = 0; sz = 0; }
                const void* src = A + (size_t)grow * K + k0 + cc * 8;
                uint32_t dst = sbuf + (uint32_t)(row * RSB + cc * 16);
                asm volatile("cp.async.ca.shared.global [%0], [%1], 16, %2;"
                             :: "r"(dst), "l"(src), "r"(sz));
            } else {                      // B plane: 256 rows x 4 chunks
                int idx = gi - 512;
                int row = idx >> 2, cc = idx & 3;
                const void* src = B + (size_t)(n0 + row) * K + k0 + cc * 8;
                uint32_t dst = sbuf + APLANE + (uint32_t)(row * RSB + cc * 16);
                asm volatile("cp.async.cg.shared.global [%0], [%1], 16;"
                             :: "r"(dst), "l"(src));
            }
        }
        asm volatile("cp.async.commit_group;" ::: "memory");
    };

    int KT = K >> 5;
    uint32_t af0[4][4], bf0[8][2];
    uint32_t af1[4][4], bf1[8][2];

    issue_loads(0);
    issue_loads(1);
    asm volatile("cp.async.wait_group 1;" ::: "memory");
    __syncthreads();
    LOAD_FRAGS(sb, 0, af0, bf0);   // stage 0, kk=0

    for (int c = 0; c < KT; c++) {
        uint32_t sbuf = sb + (uint32_t)(c % NSTAGE) * STAGE;
        // frags for kk=16 of current stage; their latency hides under MMA(buf0)
        LOAD_FRAGS(sbuf, 16, af1, bf1);
        MMA_TILE(af0, bf0);

        if (c + 1 < KT) {
            // make stage c+1 visible, recycle stage c-1, prefetch its kk=0 frags
            asm volatile("cp.async.wait_group 0;" ::: "memory");
            __syncthreads();
            if (c + 2 < KT) issue_loads(c + 2);
            uint32_t nbuf = sb + (uint32_t)((c + 1) % NSTAGE) * STAGE;
            LOAD_FRAGS(nbuf, 0, af0, bf0);
        }
        MMA_TILE(af1, bf1);
    }

    __syncthreads();
    // epilogue
#pragma unroll
    for (int mi = 0; mi < 4; mi++) {
#pragma unroll
        for (int ni = 0; ni < 8; ni++) {
            int r0 = m0 + wm * 64 + mi * 16 + (lane >> 2);
            int col = n0 + wn * 64 + ni * 8 + (lane & 3) * 2;
            float bx = 0.f, by = 0.f;
            if (bias) { bx = bias[col]; by = bias[col + 1]; }
            float2 v0, v1;
            v0.x = acc[mi][ni][0] + bx; v0.y = acc[mi][ni][1] + by;
            v1.x = acc[mi][ni][2] + bx; v1.y = acc[mi][ni][3] + by;
            if (r0 < M) {
                size_t off = (size_t)r0 * N + col;
                if (RES) { float2 rr = *(const float2*)&res[off]; v0.x += rr.x; v0.y += rr.y; }
                *(float2*)&C[off] = v0;
            }
            if (r0 + 8 < M) {
                size_t off = (size_t)(r0 + 8) * N + col;
                if (RES) { float2 rr = *(const float2*)&res[off]; v1.x += rr.x; v1.y += rr.y; }
                *(float2*)&C[off] = v1;
            }
        }
    }
}

// ---------------- LayerNorm -> fp16 plane ------------------------------------
template<int W>
__global__ void __launch_bounds__(256) ln16(const float* __restrict__ x,
                                            const float* __restrict__ g,
                                            const float* __restrict__ b,
                                            __half* __restrict__ o16)
{
    constexpr int V = W / 1024;
    __shared__ float red0[8], red1[8];
    __shared__ float stats[2];
    size_t rb = (size_t)blockIdx.x * W;
    const float4* xr = (const float4*)(x + rb);
    float4 vv[V];
    float s = 0.f, s2 = 0.f;
#pragma unroll
    for (int i = 0; i < V; i++) {
        float4 t = xr[threadIdx.x + i * 256];
        vv[i] = t;
        s  += t.x + t.y + t.z + t.w;
        s2 += t.x*t.x + t.y*t.y + t.z*t.z + t.w*t.w;
    }
#pragma unroll
    for (int o = 16; o; o >>= 1) {
        s  += __shfl_xor_sync(0xffffffffu, s,  o);
        s2 += __shfl_xor_sync(0xffffffffu, s2, o);
    }
    if ((threadIdx.x & 31) == 0) { red0[threadIdx.x >> 5] = s; red1[threadIdx.x >> 5] = s2; }
    __syncthreads();
    if (threadIdx.x == 0) {
        float a = 0.f, c = 0.f;
#pragma unroll
        for (int i = 0; i < 8; i++) { a += red0[i]; c += red1[i]; }
        float mu  = a / (float)W;
        float var = c / (float)W - mu * mu;
        stats[0] = mu;
        stats[1] = rsqrtf(var + LN_EPS);
    }
    __syncthreads();
    float mu = stats[0], inv = stats[1];
    const float4* g4 = (const float4*)g;
    const float4* b4 = (const float4*)b;
#pragma unroll
    for (int i = 0; i < V; i++) {
        int c = threadIdx.x + i * 256;
        float4 gg = g4[c], bb = b4[c], t = vv[i], o;
        o.x = (t.x - mu) * inv * gg.x + bb.x;
        o.y = (t.y - mu) * inv * gg.y + bb.y;
        o.z = (t.z - mu) * inv * gg.z + bb.z;
        o.w = (t.w - mu) * inv * gg.w + bb.w;
        ((uint2*)(o16 + rb))[c] = pack16(o);
    }
}

// ---------------- fused SiLU(x1)*x2 -> LayerNorm -> fp16 (from fused h12) ---
__global__ void __launch_bounds__(256) silu_ln16(const float* __restrict__ h12,
                                                 const float* __restrict__ g,
                                                 const float* __restrict__ b,
                                                 __half* __restrict__ o16)
{
    constexpr int W = HDIM;
    constexpr int V = W / 1024;
    __shared__ float red0[8], red1[8];
    __shared__ float stats[2];
    size_t rb12 = (size_t)blockIdx.x * (2 * HDIM);
    size_t rb   = (size_t)blockIdx.x * W;
    const float4* ar = (const float4*)(h12 + rb12);
    const float4* cr = (const float4*)(h12 + rb12 + HDIM);
    float4 vv[V];
    float s = 0.f, s2 = 0.f;
#pragma unroll
    for (int i = 0; i < V; i++) {
        float4 a = ar[threadIdx.x + i * 256];
        float4 c = cr[threadIdx.x + i * 256];
        float4 t;
        t.x = a.x / (1.f + __expf(-a.x)) * c.x;
        t.y = a.y / (1.f + __expf(-a.y)) * c.y;
        t.z = a.z / (1.f + __expf(-a.z)) * c.z;
        t.w = a.w / (1.f + __expf(-a.w)) * c.w;
        vv[i] = t;
        s  += t.x + t.y + t.z + t.w;
        s2 += t.x*t.x + t.y*t.y + t.z*t.z + t.w*t.w;
    }
#pragma unroll
    for (int o = 16; o; o >>= 1) {
        s  += __shfl_xor_sync(0xffffffffu, s,  o);
        s2 += __shfl_xor_sync(0xffffffffu, s2, o);
    }
    if ((threadIdx.x & 31) == 0) { red0[threadIdx.x >> 5] = s; red1[threadIdx.x >> 5] = s2; }
    __syncthreads();
    if (threadIdx.x == 0) {
        float a = 0.f, c = 0.f;
#pragma unroll
        for (int i = 0; i < 8; i++) { a += red0[i]; c += red1[i]; }
        float mu  = a / (float)W;
        float var = c / (float)W - mu * mu;
        stats[0] = mu;
        stats[1] = rsqrtf(var + LN_EPS);
    }
    __syncthreads();
    float mu = stats[0], inv = stats[1];
    const float4* g4 = (const float4*)g;
    const float4* b4 = (const float4*)b;
#pragma unroll
    for (int i = 0; i < V; i++) {
        int c = threadIdx.x + i * 256;
        float4 gg = g4[c], bb = b4[c], t = vv[i], o;
        o.x = (t.x - mu) * inv * gg.x + bb.x;
        o.y = (t.y - mu) * inv * gg.y + bb.y;
        o.z = (t.z - mu) * inv * gg.z + bb.z;
        o.w = (t.w - mu) * inv * gg.w + bb.w;
        ((uint2*)(o16 + rb))[c] = pack16(o);
    }
}

// ---------------- RoPE on q,k in fused qkv buffer; scale q ------------------
__global__ void __launch_bounds__(256) rope_kernel(float* __restrict__ qkv,
                                                   const float* __restrict__ cosb,
                                                   const float* __restrict__ sinb)
{
    const float scale = 0.125f;
    int row = blockIdx.x;
    int n = row % NTOK;
    float4* qr = (float4*)(qkv + (size_t)row * STRQ);
    float4* kr = (float4*)(qkv + (size_t)row * STRQ + DMODEL);
    int ci = threadIdx.x;
    if (n == 0) {
        float4 t = qr[ci];
        t.x *= scale; t.y *= scale; t.z *= scale; t.w *= scale;
        qr[ci] = t;
        return;
    }
    int d = (ci * 4) & 63;
    const float4 cs = *(const float4*)(cosb + (size_t)(n - 1) * HD + d);
    const float4 sn = *(const float4*)(sinb + (size_t)(n - 1) * HD + d);
    float4 t = qr[ci], o;
    o.x = t.x * cs.x - t.y * sn.x;
    o.y = t.y * cs.y + t.x * sn.y;
    o.z = t.z * cs.z - t.w * sn.z;
    o.w = t.w * cs.w + t.z * sn.w;
    o.x *= scale; o.y *= scale; o.z *= scale; o.w *= scale;
    qr[ci] = o;
    t = kr[ci];
    o.x = t.x * cs.x - t.y * sn.x;
    o.y = t.y * cs.y + t.x * sn.y;
    o.z = t.z * cs.z - t.w * sn.z;
    o.w = t.w * cs.w + t.z * sn.w;
    kr[ci] = o;
}

// ---------------- attention v3: contiguous-key ownership --------------------
// KsTm[d][j] = K[j+1][d] (keys 1..256), k0[d] = K[0][d].
// Thread `lane` owns keys j = lane*8 .. lane*8+7 (i.e. kk = j+1).
// Explicit float-offset layout; psH padded to 16B alignment.
#define OFF_KSTM 0
#define OFF_K0   (OFF_KSTM + 64 * 264)         // 16896
#define OFF_VS   (OFF_K0 + 64)                 // 16960
#define OFF_BS   (OFF_VS + 257 * 65)           // 33665
#define OFF_QS   (OFF_BS + 964)                // 34629
#define OFF_P0   (OFF_QS + 8 * 8 * 64)         // 38725
#define OFF_PSH  ((OFF_P0 + 64 + 3) & ~3)      // 38792 (16B aligned)
#define ATTN_SMEM_BYTES (OFF_PSH * 4 + 8 * 8 * 264 * 2)   // 188960

#define KTM_STR 264

__global__ void __launch_bounds__(256) attn_kernel(const float* __restrict__ qkv,
                                                   const float* __restrict__ table,
                                                   float* __restrict__ out)
{
    extern __shared__ __align__(16) float sm[];
    float* KsTm = sm + OFF_KSTM;           // [64][264]
    float* k0   = sm + OFF_K0;             // [64]
    float* Vs   = sm + OFF_VS;             // [257][65]
    float* bs   = sm + OFF_BS;             // [964]
    float* qs   = sm + OFF_QS;             // [8w][8][64]
    float* p0s  = sm + OFF_P0;             // [8w][8]
    __half* psH = (__half*)(sm + OFF_PSH); // [8w][8][264] halves, 16B aligned

    int bh = blockIdx.x;
    int b = bh >> 4, h = bh & 15;
    int tid = threadIdx.x, lane = tid & 31, w = tid >> 5;
    const float* qg = qkv + (size_t)b * NTOK * STRQ + h * HD;
    const float* kg = qg + DMODEL;
    const float* vg = qg + 2 * DMODEL;

    for (int i = tid; i < NTOK * HD; i += 256) {
        int r = i >> 6, c = i & 63;
        float kv = kg[(size_t)r * STRQ + c];
        Vs[r * 65 + c] = vg[(size_t)r * STRQ + c];
        if (r == 0) k0[c] = kv;
        else        KsTm[c * KTM_STR + (r - 1)] = kv;
    }
    for (int i = tid; i < 964; i += 256) bs[i] = table[(size_t)i * NHEAD + h];
    __syncthreads();

    float* qsw = qs + w * 8 * 64;
    float* p0w = p0s + w * 8;
    __half* psw = psH + w * 8 * 264;

    for (int qb = w * 8; qb < NTOK; qb += 64) {
#pragma unroll
        for (int a = 0; a < 8; a++) {
            int qi = qb + a;
            float v0 = 0.f, v1 = 0.f;
            if (qi < NTOK) {
                v0 = qg[(size_t)qi * STRQ + lane];
                v1 = qg[(size_t)qi * STRQ + lane + 32];
            }
            qsw[a * 64 + lane]      = v0;
            qsw[a * 64 + lane + 32] = v1;
        }
        __syncwarp();

        // QK^T for owned keys + CLS key
        float e[8][8], e0[8];
#pragma unroll
        for (int a = 0; a < 8; a++) {
            e0[a] = 0.f;
#pragma unroll
            for (int i = 0; i < 8; i++) e[a][i] = 0.f;
        }
        for (int d = 0; d < 64; d++) {
            float4 ka = *(float4*)&KsTm[d * KTM_STR + lane * 8];
            float4 kb = *(float4*)&KsTm[d * KTM_STR + lane * 8 + 4];
            float kz = k0[d];
#pragma unroll
            for (int a = 0; a < 8; a++) {
                float qv = qsw[a * 64 + d];
                e[a][0] += qv * ka.x; e[a][1] += qv * ka.y;
                e[a][2] += qv * ka.z; e[a][3] += qv * ka.w;
                e[a][4] += qv * kb.x; e[a][5] += qv * kb.y;
                e[a][6] += qv * kb.z; e[a][7] += qv * kb.w;
                e0[a]   += qv * kz;
            }
        }

        // softmax per q-row; write P fp16 (cols shifted: col j = key j+1)
#pragma unroll
        for (int a = 0; a < 8; a++) {
            int qi = qb + a;
            bool q0 = (qi == 0);
            int pq = qi - 1, chq = pq >> 4, cwq = pq & 15;
            float ee[8];
#pragma unroll
            for (int i = 0; i < 8; i++) {
                int pk = lane * 8 + i;
                int idx = q0 ? 961
                             : (chq - (pk >> 4) + 15) * 31 + (cwq - (pk & 15) + 15);
                ee[i] = e[a][i] + bs[idx];
            }
            float e0b = e0[a] + bs[q0 ? 963 : 962];
            float mx = e0b;
#pragma unroll
            for (int i = 0; i < 8; i++) mx = fmaxf(mx, ee[i]);
#pragma unroll
            for (int o = 16; o; o >>= 1) mx = fmaxf(mx, __shfl_xor_sync(0xffffffffu, mx, o));
            float p0v = __expf(e0b - mx);
            float sum = (lane == 0) ? p0v : 0.f;
#pragma unroll
            for (int i = 0; i < 8; i++) { ee[i] = __expf(ee[i] - mx); sum += ee[i]; }
#pragma unroll
            for (int o = 16; o; o >>= 1) sum += __shfl_xor_sync(0xffffffffu, sum, o);
            float inv = 1.f / sum;
            __half2 h0 = __floats2half2_rn(ee[0] * inv, ee[1] * inv);
            __half2 h1 = __floats2half2_rn(ee[2] * inv, ee[3] * inv);
            __half2 h2 = __floats2half2_rn(ee[4] * inv, ee[5] * inv);
            __half2 h3 = __floats2half2_rn(ee[6] * inv, ee[7] * inv);
            uint4 pk4;
            pk4.x = *(uint32_t*)&h0; pk4.y = *(uint32_t*)&h1;
            pk4.z = *(uint32_t*)&h2; pk4.w = *(uint32_t*)&h3;
            *(uint4*)&psw[a * 264 + lane * 8] = pk4;
            if (lane == 0) p0w[a] = p0v * inv;
        }
        __syncwarp();

        // AV: keys 1..256 via psw cols 0..255, then CLS key
        float av[8][2];
#pragma unroll
        for (int a = 0; a < 8; a++) { av[a][0] = 0.f; av[a][1] = 0.f; }

        for (int jq = 0; jq < 64; jq++) {
            int j = jq * 4;
            float v00 = Vs[(j + 1) * 65 + lane], v01 = Vs[(j + 1) * 65 + lane + 32];
            float v10 = Vs[(j + 2) * 65 + lane], v11 = Vs[(j + 2) * 65 + lane + 32];
            float v20 = Vs[(j + 3) * 65 + lane], v21 = Vs[(j + 3) * 65 + lane + 32];
            float v30 = Vs[(j + 4) * 65 + lane], v31 = Vs[(j + 4) * 65 + lane + 32];
#pragma unroll
            for (int a = 0; a < 8; a++) {
                uint2 praw = *(uint2*)&psw[a * 264 + j];
                float2 f01 = __half22float2(*(__half2*)&praw.x);
                float2 f23 = __half22float2(*(__half2*)&praw.y);
                av[a][0] += f01.x * v00 + f01.y * v10 + f23.x * v20 + f23.y * v30;
                av[a][1] += f01.x * v01 + f01.y * v11 + f23.x * v21 + f23.y * v31;
            }
        }
        {
            float vz0 = Vs[lane], vz1 = Vs[lane + 32];
#pragma unroll
            for (int a = 0; a < 8; a++) {
                float p0v = p0w[a];
                av[a][0] += p0v * vz0;
                av[a][1] += p0v * vz1;
            }
        }
#pragma unroll
        for (int a = 0; a < 8; a++) {
            int qi = qb + a;
            if (qi < NTOK) {
                size_t off = ((size_t)b * NTOK + qi) * DMODEL + h * HD;
                out[off + lane]      = av[a][0];
                out[off + lane + 32] = av[a][1];
            }
        }
        __syncwarp();
    }
}

// ---------------- launch -----------------------------------------------------
extern "C" void kernel_launch(void* const* d_in, const int* in_sizes, int n_in,
                              void* d_out, int out_size)
{
    const float* x        = (const float*)d_in[0];
    const float* rope_cos = (const float*)d_in[1];
    const float* rope_sin = (const float*)d_in[2];
    const float* q_w      = (const float*)d_in[3];
    const float* q_b      = (const float*)d_in[4];
    const float* k_w      = (const float*)d_in[5];
    const float* v_w      = (const float*)d_in[6];
    const float* v_b      = (const float*)d_in[7];
    const float* table    = (const float*)d_in[8];
    const float* in_g     = (const float*)d_in[9];
    const float* in_b     = (const float*)d_in[10];
    const float* proj_w   = (const float*)d_in[11];
    const float* proj_b   = (const float*)d_in[12];
    const float* n1g      = (const float*)d_in[13];
    const float* n1b      = (const float*)d_in[14];
    const float* n2g      = (const float*)d_in[15];
    const float* n2b      = (const float*)d_in[16];
    const float* w1       = (const float*)d_in[17];
    const float* w1b      = (const float*)d_in[18];
    const float* w2       = (const float*)d_in[19];
    const float* w2b      = (const float*)d_in[20];
    const float* fg       = (const float*)d_in[21];
    const float* fb       = (const float*)d_in[22];
    const float* w3       = (const float*)d_in[23];
    const float* w3b      = (const float*)d_in[24];
    float* out = (float*)d_out;

    float *qkv, *att, *x1, *h12, *qkvb, *w12b;
    __half *a16, *h16, *qkvw16, *pw16, *w1216, *w316;
    cudaGetSymbolAddress((void**)&qkv,    g_qkv);
    cudaGetSymbolAddress((void**)&att,    g_att);
    cudaGetSymbolAddress((void**)&x1,     g_x1);
    cudaGetSymbolAddress((void**)&h12,    g_h12);
    cudaGetSymbolAddress((void**)&a16,    g_a16);
    cudaGetSymbolAddress((void**)&h16,    g_h16);
    cudaGetSymbolAddress((void**)&qkvw16, g_qkvw16);
    cudaGetSymbolAddress((void**)&pw16,   g_pw16);
    cudaGetSymbolAddress((void**)&w1216,  g_w1216);
    cudaGetSymbolAddress((void**)&w316,   g_w316);
    cudaGetSymbolAddress((void**)&qkvb,   g_qkvb);
    cudaGetSymbolAddress((void**)&w12b,   g_w12b);

    cudaFuncSetAttribute(attn_kernel, cudaFuncAttributeMaxDynamicSharedMemorySize, ATTN_SMEM_BYTES);
    cudaFuncSetAttribute(tgemm<false>, cudaFuncAttributeMaxDynamicSharedMemorySize, SMEM_G);
    cudaFuncSetAttribute(tgemm<true>,  cudaFuncAttributeMaxDynamicSharedMemorySize, SMEM_G);

    dim3 blk(256);
    dim3 gQKV(3 * DMODEL / 256, (T_TOK + 127) / 128);   // (12, 129)
    dim3 gP(DMODEL / 256,       (T_TOK + 127) / 128);   // (4, 129)
    dim3 gW12(2 * HDIM / 256,   (T_TOK + 127) / 128);   // (32, 129)

    const int n4_1M = DMODEL * DMODEL / 4;    // 262144
    const int n4_4M = HDIM * DMODEL / 4;      // 1048576

    // #1: convert q/k/v/proj weights
    cvt4<<<dim3((n4_1M + 255) / 256, 4), blk>>>(
        q_w, qkvw16,
        k_w, qkvw16 + (size_t)DMODEL * DMODEL,
        v_w, qkvw16 + (size_t)2 * DMODEL * DMODEL,
        proj_w, pw16, n4_1M);
    // #2: pack biases
    pack_biases<<<(3 * DMODEL + 2 * HDIM + 255) / 256, blk>>>(q_b, v_b, w1b, w2b, qkvb, w12b);
    // #3: norm1 -> fp16
    ln16<DMODEL><<<T_TOK, blk>>>(x, n1g, n1b, a16);
    // #4: fused QKV projection
    tgemm<false><<<gQKV, blk, SMEM_G>>>(a16, qkvw16, qkvb, nullptr, qkv, T_TOK, 3 * DMODEL, DMODEL);
    // #5: RoPE + q scaling
    rope_kernel<<<T_TOK, blk>>>(qkv, rope_cos, rope_sin);
    // #6: attention
    attn_kernel<<<BATCH * NHEAD, blk, ATTN_SMEM_BYTES>>>(qkv, table, att);
    // #7: convert FFN weights (needed only from launch #11 on)
    cvt4<<<dim3((n4_4M + 255) / 256, 3), blk>>>(
        w1, w1216,
        w2, w1216 + (size_t)HDIM * DMODEL,
        w3, w316,
        w3, w316, n4_4M);
    // #8: inner LN -> fp16
    ln16<DMODEL><<<T_TOK, blk>>>(att, in_g, in_b, a16);
    // #9: proj (+ residual with x) -> x1
    tgemm<true><<<gP, blk, SMEM_G>>>(a16, pw16, proj_b, x, x1, T_TOK, DMODEL, DMODEL);
    // #10: norm2 -> fp16
    ln16<DMODEL><<<T_TOK, blk>>>(x1, n2g, n2b, a16);
    // #11: fused FFN up projection (w1|w2)
    tgemm<false><<<gW12, blk, SMEM_G>>>(a16, w1216, w12b, nullptr, h12, T_TOK, 2 * HDIM, DMODEL);
    // #12: silu(x1h)*x2h -> ffn LN -> fp16
    silu_ln16<<<T_TOK, blk>>>(h12, fg, fb, h16);
    // #13: down projection + residual -> out
    tgemm<true><<<gP, blk, SMEM_G>>>(h16, w316, w3b, x1, out, T_TOK, DMODEL, HDIM);
}

// round 12
// speedup vs baseline: 1.0995x; 1.0705x over previous
#include <cuda_runtime.h>
#include <cuda_fp16.h>
#include <stdint.h>
#include <math.h>

#define NTOK   257
#define BATCH  64
#define T_TOK  (BATCH * NTOK)   // 16448
#define DMODEL 1024
#define NHEAD  16
#define HD     64
#define HDIM   4096
#define LN_EPS 1e-5f
#define STRQ   3072              // fused qkv row stride

// ---------------- scratch (device globals; no allocations allowed) ----------
__device__ __align__(16) float g_qkv[(size_t)T_TOK * STRQ];
__device__ __align__(16) float g_att[(size_t)T_TOK * DMODEL];
__device__ __align__(16) float g_x1 [(size_t)T_TOK * DMODEL];
__device__ __align__(16) float g_h12[(size_t)T_TOK * 2 * HDIM];

__device__ __align__(16) __half g_a16[(size_t)T_TOK * DMODEL];
__device__ __align__(16) __half g_h16[(size_t)T_TOK * HDIM];
__device__ __align__(16) __half g_qkvw16[(size_t)3 * DMODEL * DMODEL];
__device__ __align__(16) __half g_pw16[(size_t)DMODEL * DMODEL];
__device__ __align__(16) __half g_w1216[(size_t)2 * HDIM * DMODEL];
__device__ __align__(16) __half g_w316[(size_t)DMODEL * HDIM];
__device__ __align__(16) float  g_qkvb[3 * DMODEL];
__device__ __align__(16) float  g_w12b[2 * HDIM];

// ---------------- fp32 -> fp16 helpers --------------------------------------
__device__ __forceinline__ uint2 pack16(float4 t)
{
    __half2 a = __floats2half2_rn(t.x, t.y);
    __half2 b = __floats2half2_rn(t.z, t.w);
    uint2 r;
    r.x = *(uint32_t*)&a;
    r.y = *(uint32_t*)&b;
    return r;
}

// one launch converts up to 4 weight matrices (blockIdx.y selects)
__global__ void __launch_bounds__(256) cvt4(const float* __restrict__ s0, __half* __restrict__ d0,
                                            const float* __restrict__ s1, __half* __restrict__ d1,
                                            const float* __restrict__ s2, __half* __restrict__ d2,
                                            const float* __restrict__ s3, __half* __restrict__ d3,
                                            int n4)
{
    int i = blockIdx.x * 256 + threadIdx.x;
    if (i >= n4) return;
    const float* s = (blockIdx.y == 0) ? s0 : (blockIdx.y == 1) ? s1 : (blockIdx.y == 2) ? s2 : s3;
    __half*      d = (blockIdx.y == 0) ? d0 : (blockIdx.y == 1) ? d1 : (blockIdx.y == 2) ? d2 : d3;
    ((uint2*)d)[i] = pack16(((const float4*)s)[i]);
}

__global__ void __launch_bounds__(256) pack_biases(const float* __restrict__ qb,
                                                   const float* __restrict__ vb,
                                                   const float* __restrict__ b1,
                                                   const float* __restrict__ b2,
                                                   float* __restrict__ qkvb,
                                                   float* __restrict__ w12b)
{
    int i = blockIdx.x * 256 + threadIdx.x;
    if (i < 3 * DMODEL) {
        qkvb[i] = (i < DMODEL) ? qb[i] : ((i < 2 * DMODEL) ? 0.f : vb[i - 2 * DMODEL]);
    } else {
        int j = i - 3 * DMODEL;
        if (j < 2 * HDIM) w12b[j] = (j < HDIM) ? b1[j] : b2[j - HDIM];
    }
}

// ---------------- mma.sync GEMM: C = A*B^T (+bias)(+res), fp32 out ----------
// CTA tile 128x128, 8 warps (2x4), warp tile 64x32, K chunk 32, 3-stage
// cp.async pipeline with 2 groups in flight, 2 CTAs/SM.
#define RSB    80                 // smem row stride bytes (40 halves)
#define APLANE (128 * RSB)        // 10240
#define BPLANE (128 * RSB)        // 10240
#define STAGE  (APLANE + BPLANE)  // 20480
#define NSTAGE 3
#define SMEM_G (NSTAGE * STAGE)   // 61440

#define LDSM4(r0, r1, r2, r3, addr) \
    asm volatile("ldmatrix.sync.aligned.m8n8.x4.shared.b16 {%0,%1,%2,%3}, [%4];" \
                 : "=r"(r0), "=r"(r1), "=r"(r2), "=r"(r3) : "r"(addr))

#define MMA16816(c, a, b) \
    asm volatile("mma.sync.aligned.m16n8k16.row.col.f32.f16.f16.f32 " \
                 "{%0,%1,%2,%3}, {%4,%5,%6,%7}, {%8,%9}, {%0,%1,%2,%3};" \
                 : "+f"((c)[0]), "+f"((c)[1]), "+f"((c)[2]), "+f"((c)[3]) \
                 : "r"((a)[0]), "r"((a)[1]), "r"((a)[2]), "r"((a)[3]), \
                   "r"((b)[0]), "r"((b)[1]))

template<bool RES>
__global__ void __launch_bounds__(256, 2) tgemm(const __half* __restrict__ A,
                                                const __half* __restrict__ B,
                                                const float* __restrict__ bias,
                                                const float* __restrict__ res,
                                                float* __restrict__ C,
                                                int M, int N, int K)
{
    extern __shared__ __align__(16) char dsm[];
    uint32_t sb = (uint32_t)__cvta_generic_to_shared(dsm);

    int tid = threadIdx.x, lane = tid & 31, warp = tid >> 5;
    int wm = warp >> 2, wn = warp & 3;           // warp grid 2 x 4
    int m0 = blockIdx.y * 128, n0 = blockIdx.x * 128;

    float acc[4][4][4];
#pragma unroll
    for (int i = 0; i < 4; i++)
#pragma unroll
        for (int j = 0; j < 4; j++)
#pragma unroll
            for (int r = 0; r < 4; r++) acc[i][j][r] = 0.f;

    auto issue_loads = [&](int c) {
        int k0 = c * 32;
        uint32_t sbuf = sb + (uint32_t)(c % NSTAGE) * STAGE;
#pragma unroll
        for (int i = 0; i < 4; i++) {
            int gi = i * 256 + tid;       // 0..1023
            int p = gi >> 9;              // 0:A 1:B
            int idx = gi & 511;
            int row = idx >> 2, cc = idx & 3;
            if (p == 0) {
                int grow = m0 + row;
                int sz = 16;
                if (grow >= M) { grow = 0; sz = 0; }
                const void* src = A + (size_t)grow * K + k0 + cc * 8;
                uint32_t dst = sbuf + (uint32_t)(row * RSB + cc * 16);
                asm volatile("cp.async.ca.shared.global [%0], [%1], 16, %2;"
                             :: "r"(dst), "l"(src), "r"(sz));
            } else {
                const void* src = B + (size_t)(n0 + row) * K + k0 + cc * 8;
                uint32_t dst = sbuf + APLANE + (uint32_t)(row * RSB + cc * 16);
                asm volatile("cp.async.cg.shared.global [%0], [%1], 16;"
                             :: "r"(dst), "l"(src));
            }
        }
        asm volatile("cp.async.commit_group;" ::: "memory");
    };

    int KT = K >> 5;
    issue_loads(0);
    issue_loads(1);
    asm volatile("cp.async.wait_group 1;" ::: "memory");
    __syncthreads();

    for (int c = 0; c < KT; c++) {
        uint32_t sbuf = sb + (uint32_t)(c % NSTAGE) * STAGE;
        if (c + 2 < KT) issue_loads(c + 2);   // 2 groups in flight

#pragma unroll
        for (int kk = 0; kk < 32; kk += 16) {
            uint32_t af[4][4], bf[4][2];
#pragma unroll
            for (int mi = 0; mi < 4; mi++) {
                int arow = wm * 64 + mi * 16 + (lane & 15);
                uint32_t aoff = (uint32_t)(arow * RSB + (kk + (lane >> 4) * 8) * 2);
                LDSM4(af[mi][0], af[mi][1], af[mi][2], af[mi][3], sbuf + aoff);
            }
#pragma unroll
            for (int nj = 0; nj < 2; nj++) {
                int g = lane >> 3;
                int nrow = wn * 32 + nj * 16 + (g >> 1) * 8 + (lane & 7);
                uint32_t boff = (uint32_t)(nrow * RSB + (kk + (g & 1) * 8) * 2);
                LDSM4(bf[nj*2][0], bf[nj*2][1], bf[nj*2+1][0], bf[nj*2+1][1],
                      sbuf + APLANE + boff);
            }
#pragma unroll
            for (int mi = 0; mi < 4; mi++)
#pragma unroll
                for (int ni = 0; ni < 4; ni++)
                    MMA16816(acc[mi][ni], af[mi], bf[ni]);
        }

        if (c + 1 < KT) {
            asm volatile("cp.async.wait_group 1;" ::: "memory");
            __syncthreads();
        }
    }

    // epilogue
#pragma unroll
    for (int mi = 0; mi < 4; mi++) {
#pragma unroll
        for (int ni = 0; ni < 4; ni++) {
            int r0 = m0 + wm * 64 + mi * 16 + (lane >> 2);
            int col = n0 + wn * 32 + ni * 8 + (lane & 3) * 2;
            float bx = 0.f, by = 0.f;
            if (bias) { bx = bias[col]; by = bias[col + 1]; }
            float2 v0, v1;
            v0.x = acc[mi][ni][0] + bx; v0.y = acc[mi][ni][1] + by;
            v1.x = acc[mi][ni][2] + bx; v1.y = acc[mi][ni][3] + by;
            if (r0 < M) {
                size_t off = (size_t)r0 * N + col;
                if (RES) { float2 rr = *(const float2*)&res[off]; v0.x += rr.x; v0.y += rr.y; }
                *(float2*)&C[off] = v0;
            }
            if (r0 + 8 < M) {
                size_t off = (size_t)(r0 + 8) * N + col;
                if (RES) { float2 rr = *(const float2*)&res[off]; v1.x += rr.x; v1.y += rr.y; }
                *(float2*)&C[off] = v1;
            }
        }
    }
}

// ---------------- LayerNorm -> fp16 plane ------------------------------------
template<int W>
__global__ void __launch_bounds__(256) ln16(const float* __restrict__ x,
                                            const float* __restrict__ g,
                                            const float* __restrict__ b,
                                            __half* __restrict__ o16)
{
    constexpr int V = W / 1024;
    __shared__ float red0[8], red1[8];
    __shared__ float stats[2];
    size_t rb = (size_t)blockIdx.x * W;
    const float4* xr = (const float4*)(x + rb);
    float4 vv[V];
    float s = 0.f, s2 = 0.f;
#pragma unroll
    for (int i = 0; i < V; i++) {
        float4 t = xr[threadIdx.x + i * 256];
        vv[i] = t;
        s  += t.x + t.y + t.z + t.w;
        s2 += t.x*t.x + t.y*t.y + t.z*t.z + t.w*t.w;
    }
#pragma unroll
    for (int o = 16; o; o >>= 1) {
        s  += __shfl_xor_sync(0xffffffffu, s,  o);
        s2 += __shfl_xor_sync(0xffffffffu, s2, o);
    }
    if ((threadIdx.x & 31) == 0) { red0[threadIdx.x >> 5] = s; red1[threadIdx.x >> 5] = s2; }
    __syncthreads();
    if (threadIdx.x == 0) {
        float a = 0.f, c = 0.f;
#pragma unroll
        for (int i = 0; i < 8; i++) { a += red0[i]; c += red1[i]; }
        float mu  = a / (float)W;
        float var = c / (float)W - mu * mu;
        stats[0] = mu;
        stats[1] = rsqrtf(var + LN_EPS);
    }
    __syncthreads();
    float mu = stats[0], inv = stats[1];
    const float4* g4 = (const float4*)g;
    const float4* b4 = (const float4*)b;
#pragma unroll
    for (int i = 0; i < V; i++) {
        int c = threadIdx.x + i * 256;
        float4 gg = g4[c], bb = b4[c], t = vv[i], o;
        o.x = (t.x - mu) * inv * gg.x + bb.x;
        o.y = (t.y - mu) * inv * gg.y + bb.y;
        o.z = (t.z - mu) * inv * gg.z + bb.z;
        o.w = (t.w - mu) * inv * gg.w + bb.w;
        ((uint2*)(o16 + rb))[c] = pack16(o);
    }
}

// ---------------- fused SiLU(x1)*x2 -> LayerNorm -> fp16 (from fused h12) ---
__global__ void __launch_bounds__(256) silu_ln16(const float* __restrict__ h12,
                                                 const float* __restrict__ g,
                                                 const float* __restrict__ b,
                                                 __half* __restrict__ o16)
{
    constexpr int W = HDIM;
    constexpr int V = W / 1024;
    __shared__ float red0[8], red1[8];
    __shared__ float stats[2];
    size_t rb12 = (size_t)blockIdx.x * (2 * HDIM);
    size_t rb   = (size_t)blockIdx.x * W;
    const float4* ar = (const float4*)(h12 + rb12);
    const float4* cr = (const float4*)(h12 + rb12 + HDIM);
    float4 vv[V];
    float s = 0.f, s2 = 0.f;
#pragma unroll
    for (int i = 0; i < V; i++) {
        float4 a = ar[threadIdx.x + i * 256];
        float4 c = cr[threadIdx.x + i * 256];
        float4 t;
        t.x = a.x / (1.f + __expf(-a.x)) * c.x;
        t.y = a.y / (1.f + __expf(-a.y)) * c.y;
        t.z = a.z / (1.f + __expf(-a.z)) * c.z;
        t.w = a.w / (1.f + __expf(-a.w)) * c.w;
        vv[i] = t;
        s  += t.x + t.y + t.z + t.w;
        s2 += t.x*t.x + t.y*t.y + t.z*t.z + t.w*t.w;
    }
#pragma unroll
    for (int o = 16; o; o >>= 1) {
        s  += __shfl_xor_sync(0xffffffffu, s,  o);
        s2 += __shfl_xor_sync(0xffffffffu, s2, o);
    }
    if ((threadIdx.x & 31) == 0) { red0[threadIdx.x >> 5] = s; red1[threadIdx.x >> 5] = s2; }
    __syncthreads();
    if (threadIdx.x == 0) {
        float a = 0.f, c = 0.f;
#pragma unroll
        for (int i = 0; i < 8; i++) { a += red0[i]; c += red1[i]; }
        float mu  = a / (float)W;
        float var = c / (float)W - mu * mu;
        stats[0] = mu;
        stats[1] = rsqrtf(var + LN_EPS);
    }
    __syncthreads();
    float mu = stats[0], inv = stats[1];
    const float4* g4 = (const float4*)g;
    const float4* b4 = (const float4*)b;
#pragma unroll
    for (int i = 0; i < V; i++) {
        int c = threadIdx.x + i * 256;
        float4 gg = g4[c], bb = b4[c], t = vv[i], o;
        o.x = (t.x - mu) * inv * gg.x + bb.x;
        o.y = (t.y - mu) * inv * gg.y + bb.y;
        o.z = (t.z - mu) * inv * gg.z + bb.z;
        o.w = (t.w - mu) * inv * gg.w + bb.w;
        ((uint2*)(o16 + rb))[c] = pack16(o);
    }
}

// ---------------- RoPE on q,k in fused qkv buffer; scale q ------------------
__global__ void __launch_bounds__(256) rope_kernel(float* __restrict__ qkv,
                                                   const float* __restrict__ cosb,
                                                   const float* __restrict__ sinb)
{
    const float scale = 0.125f;
    int row = blockIdx.x;
    int n = row % NTOK;
    float4* qr = (float4*)(qkv + (size_t)row * STRQ);
    float4* kr = (float4*)(qkv + (size_t)row * STRQ + DMODEL);
    int ci = threadIdx.x;
    if (n == 0) {
        float4 t = qr[ci];
        t.x *= scale; t.y *= scale; t.z *= scale; t.w *= scale;
        qr[ci] = t;
        return;
    }
    int d = (ci * 4) & 63;
    const float4 cs = *(const float4*)(cosb + (size_t)(n - 1) * HD + d);
    const float4 sn = *(const float4*)(sinb + (size_t)(n - 1) * HD + d);
    float4 t = qr[ci], o;
    o.x = t.x * cs.x - t.y * sn.x;
    o.y = t.y * cs.y + t.x * sn.y;
    o.z = t.z * cs.z - t.w * sn.z;
    o.w = t.w * cs.w + t.z * sn.w;
    o.x *= scale; o.y *= scale; o.z *= scale; o.w *= scale;
    qr[ci] = o;
    t = kr[ci];
    o.x = t.x * cs.x - t.y * sn.x;
    o.y = t.y * cs.y + t.x * sn.y;
    o.z = t.z * cs.z - t.w * sn.z;
    o.w = t.w * cs.w + t.z * sn.w;
    kr[ci] = o;
}

// ---------------- attention v3: contiguous-key ownership --------------------
#define OFF_KSTM 0
#define OFF_K0   (OFF_KSTM + 64 * 264)         // 16896
#define OFF_VS   (OFF_K0 + 64)                 // 16960
#define OFF_BS   (OFF_VS + 257 * 65)           // 33665
#define OFF_QS   (OFF_BS + 964)                // 34629
#define OFF_P0   (OFF_QS + 8 * 8 * 64)         // 38725
#define OFF_PSH  ((OFF_P0 + 64 + 3) & ~3)      // 38792 (16B aligned)
#define ATTN_SMEM_BYTES (OFF_PSH * 4 + 8 * 8 * 264 * 2)   // 188960

#define KTM_STR 264

__global__ void __launch_bounds__(256) attn_kernel(const float* __restrict__ qkv,
                                                   const float* __restrict__ table,
                                                   float* __restrict__ out)
{
    extern __shared__ __align__(16) float sm[];
    float* KsTm = sm + OFF_KSTM;           // [64][264]
    float* k0   = sm + OFF_K0;             // [64]
    float* Vs   = sm + OFF_VS;             // [257][65]
    float* bs   = sm + OFF_BS;             // [964]
    float* qs   = sm + OFF_QS;             // [8w][8][64]
    float* p0s  = sm + OFF_P0;             // [8w][8]
    __half* psH = (__half*)(sm + OFF_PSH); // [8w][8][264] halves, 16B aligned

    int bh = blockIdx.x;
    int b = bh >> 4, h = bh & 15;
    int tid = threadIdx.x, lane = tid & 31, w = tid >> 5;
    const float* qg = qkv + (size_t)b * NTOK * STRQ + h * HD;
    const float* kg = qg + DMODEL;
    const float* vg = qg + 2 * DMODEL;

    for (int i = tid; i < NTOK * HD; i += 256) {
        int r = i >> 6, c = i & 63;
        float kv = kg[(size_t)r * STRQ + c];
        Vs[r * 65 + c] = vg[(size_t)r * STRQ + c];
        if (r == 0) k0[c] = kv;
        else        KsTm[c * KTM_STR + (r - 1)] = kv;
    }
    for (int i = tid; i < 964; i += 256) bs[i] = table[(size_t)i * NHEAD + h];
    __syncthreads();

    float* qsw = qs + w * 8 * 64;
    float* p0w = p0s + w * 8;
    __half* psw = psH + w * 8 * 264;

    for (int qb = w * 8; qb < NTOK; qb += 64) {
#pragma unroll
        for (int a = 0; a < 8; a++) {
            int qi = qb + a;
            float v0 = 0.f, v1 = 0.f;
            if (qi < NTOK) {
                v0 = qg[(size_t)qi * STRQ + lane];
                v1 = qg[(size_t)qi * STRQ + lane + 32];
            }
            qsw[a * 64 + lane]      = v0;
            qsw[a * 64 + lane + 32] = v1;
        }
        __syncwarp();

        float e[8][8], e0[8];
#pragma unroll
        for (int a = 0; a < 8; a++) {
            e0[a] = 0.f;
#pragma unroll
            for (int i = 0; i < 8; i++) e[a][i] = 0.f;
        }
        for (int d = 0; d < 64; d++) {
            float4 ka = *(float4*)&KsTm[d * KTM_STR + lane * 8];
            float4 kb = *(float4*)&KsTm[d * KTM_STR + lane * 8 + 4];
            float kz = k0[d];
#pragma unroll
            for (int a = 0; a < 8; a++) {
                float qv = qsw[a * 64 + d];
                e[a][0] += qv * ka.x; e[a][1] += qv * ka.y;
                e[a][2] += qv * ka.z; e[a][3] += qv * ka.w;
                e[a][4] += qv * kb.x; e[a][5] += qv * kb.y;
                e[a][6] += qv * kb.z; e[a][7] += qv * kb.w;
                e0[a]   += qv * kz;
            }
        }

#pragma unroll
        for (int a = 0; a < 8; a++) {
            int qi = qb + a;
            bool q0 = (qi == 0);
            int pq = qi - 1, chq = pq >> 4, cwq = pq & 15;
            float ee[8];
#pragma unroll
            for (int i = 0; i < 8; i++) {
                int pk = lane * 8 + i;
                int idx = q0 ? 961
                             : (chq - (pk >> 4) + 15) * 31 + (cwq - (pk & 15) + 15);
                ee[i] = e[a][i] + bs[idx];
            }
            float e0b = e0[a] + bs[q0 ? 963 : 962];
            float mx = e0b;
#pragma unroll
            for (int i = 0; i < 8; i++) mx = fmaxf(mx, ee[i]);
#pragma unroll
            for (int o = 16; o; o >>= 1) mx = fmaxf(mx, __shfl_xor_sync(0xffffffffu, mx, o));
            float p0v = __expf(e0b - mx);
            float sum = (lane == 0) ? p0v : 0.f;
#pragma unroll
            for (int i = 0; i < 8; i++) { ee[i] = __expf(ee[i] - mx); sum += ee[i]; }
#pragma unroll
            for (int o = 16; o; o >>= 1) sum += __shfl_xor_sync(0xffffffffu, sum, o);
            float inv = 1.f / sum;
            __half2 h0 = __floats2half2_rn(ee[0] * inv, ee[1] * inv);
            __half2 h1 = __floats2half2_rn(ee[2] * inv, ee[3] * inv);
            __half2 h2 = __floats2half2_rn(ee[4] * inv, ee[5] * inv);
            __half2 h3 = __floats2half2_rn(ee[6] * inv, ee[7] * inv);
            uint4 pk4;
            pk4.x = *(uint32_t*)&h0; pk4.y = *(uint32_t*)&h1;
            pk4.z = *(uint32_t*)&h2; pk4.w = *(uint32_t*)&h3;
            *(uint4*)&psw[a * 264 + lane * 8] = pk4;
            if (lane == 0) p0w[a] = p0v * inv;
        }
        __syncwarp();

        float av[8][2];
#pragma unroll
        for (int a = 0; a < 8; a++) { av[a][0] = 0.f; av[a][1] = 0.f; }

        for (int jq = 0; jq < 64; jq++) {
            int j = jq * 4;
            float v00 = Vs[(j + 1) * 65 + lane], v01 = Vs[(j + 1) * 65 + lane + 32];
            float v10 = Vs[(j + 2) * 65 + lane], v11 = Vs[(j + 2) * 65 + lane + 32];
            float v20 = Vs[(j + 3) * 65 + lane], v21 = Vs[(j + 3) * 65 + lane + 32];
            float v30 = Vs[(j + 4) * 65 + lane], v31 = Vs[(j + 4) * 65 + lane + 32];
#pragma unroll
            for (int a = 0; a < 8; a++) {
                uint2 praw = *(uint2*)&psw[a * 264 + j];
                float2 f01 = __half22float2(*(__half2*)&praw.x);
                float2 f23 = __half22float2(*(__half2*)&praw.y);
                av[a][0] += f01.x * v00 + f01.y * v10 + f23.x * v20 + f23.y * v30;
                av[a][1] += f01.x * v01 + f01.y * v11 + f23.x * v21 + f23.y * v31;
            }
        }
        {
            float vz0 = Vs[lane], vz1 = Vs[lane + 32];
#pragma unroll
            for (int a = 0; a < 8; a++) {
                float p0v = p0w[a];
                av[a][0] += p0v * vz0;
                av[a][1] += p0v * vz1;
            }
        }
#pragma unroll
        for (int a = 0; a < 8; a++) {
            int qi = qb + a;
            if (qi < NTOK) {
                size_t off = ((size_t)b * NTOK + qi) * DMODEL + h * HD;
                out[off + lane]      = av[a][0];
                out[off + lane + 32] = av[a][1];
            }
        }
        __syncwarp();
    }
}

// ---------------- launch -----------------------------------------------------
extern "C" void kernel_launch(void* const* d_in, const int* in_sizes, int n_in,
                              void* d_out, int out_size)
{
    const float* x        = (const float*)d_in[0];
    const float* rope_cos = (const float*)d_in[1];
    const float* rope_sin = (const float*)d_in[2];
    const float* q_w      = (const float*)d_in[3];
    const float* q_b      = (const float*)d_in[4];
    const float* k_w      = (const float*)d_in[5];
    const float* v_w      = (const float*)d_in[6];
    const float* v_b      = (const float*)d_in[7];
    const float* table    = (const float*)d_in[8];
    const float* in_g     = (const float*)d_in[9];
    const float* in_b     = (const float*)d_in[10];
    const float* proj_w   = (const float*)d_in[11];
    const float* proj_b   = (const float*)d_in[12];
    const float* n1g      = (const float*)d_in[13];
    const float* n1b      = (const float*)d_in[14];
    const float* n2g      = (const float*)d_in[15];
    const float* n2b      = (const float*)d_in[16];
    const float* w1       = (const float*)d_in[17];
    const float* w1b      = (const float*)d_in[18];
    const float* w2       = (const float*)d_in[19];
    const float* w2b      = (const float*)d_in[20];
    const float* fg       = (const float*)d_in[21];
    const float* fb       = (const float*)d_in[22];
    const float* w3       = (const float*)d_in[23];
    const float* w3b      = (const float*)d_in[24];
    float* out = (float*)d_out;

    float *qkv, *att, *x1, *h12, *qkvb, *w12b;
    __half *a16, *h16, *qkvw16, *pw16, *w1216, *w316;
    cudaGetSymbolAddress((void**)&qkv,    g_qkv);
    cudaGetSymbolAddress((void**)&att,    g_att);
    cudaGetSymbolAddress((void**)&x1,     g_x1);
    cudaGetSymbolAddress((void**)&h12,    g_h12);
    cudaGetSymbolAddress((void**)&a16,    g_a16);
    cudaGetSymbolAddress((void**)&h16,    g_h16);
    cudaGetSymbolAddress((void**)&qkvw16, g_qkvw16);
    cudaGetSymbolAddress((void**)&pw16,   g_pw16);
    cudaGetSymbolAddress((void**)&w1216,  g_w1216);
    cudaGetSymbolAddress((void**)&w316,   g_w316);
    cudaGetSymbolAddress((void**)&qkvb,   g_qkvb);
    cudaGetSymbolAddress((void**)&w12b,   g_w12b);

    cudaFuncSetAttribute(attn_kernel, cudaFuncAttributeMaxDynamicSharedMemorySize, ATTN_SMEM_BYTES);
    cudaFuncSetAttribute(tgemm<false>, cudaFuncAttributeMaxDynamicSharedMemorySize, SMEM_G);
    cudaFuncSetAttribute(tgemm<true>,  cudaFuncAttributeMaxDynamicSharedMemorySize, SMEM_G);

    dim3 blk(256);
    dim3 gQKV(3 * DMODEL / 128, (T_TOK + 127) / 128);   // (24, 129)
    dim3 gP(DMODEL / 128,       (T_TOK + 127) / 128);   // (8, 129)
    dim3 gW12(2 * HDIM / 128,   (T_TOK + 127) / 128);   // (64, 129)

    const int n4_1M = DMODEL * DMODEL / 4;    // 262144
    const int n4_4M = HDIM * DMODEL / 4;      // 1048576

    // #1: convert q/k/v/proj weights
    cvt4<<<dim3((n4_1M + 255) / 256, 4), blk>>>(
        q_w, qkvw16,
        k_w, qkvw16 + (size_t)DMODEL * DMODEL,
        v_w, qkvw16 + (size_t)2 * DMODEL * DMODEL,
        proj_w, pw16, n4_1M);
    // #2: pack biases
    pack_biases<<<(3 * DMODEL + 2 * HDIM + 255) / 256, blk>>>(q_b, v_b, w1b, w2b, qkvb, w12b);
    // #3: norm1 -> fp16
    ln16<DMODEL><<<T_TOK, blk>>>(x, n1g, n1b, a16);
    // #4: fused QKV projection
    tgemm<false><<<gQKV, blk, SMEM_G>>>(a16, qkvw16, qkvb, nullptr, qkv, T_TOK, 3 * DMODEL, DMODEL);
    // #5: RoPE + q scaling
    rope_kernel<<<T_TOK, blk>>>(qkv, rope_cos, rope_sin);
    // #6: attention
    attn_kernel<<<BATCH * NHEAD, blk, ATTN_SMEM_BYTES>>>(qkv, table, att);
    // #7: convert FFN weights (needed only from launch #11 on)
    cvt4<<<dim3((n4_4M + 255) / 256, 3), blk>>>(
        w1, w1216,
        w2, w1216 + (size_t)HDIM * DMODEL,
        w3, w316,
        w3, w316, n4_4M);
    // #8: inner LN -> fp16
    ln16<DMODEL><<<T_TOK, blk>>>(att, in_g, in_b, a16);
    // #9: proj (+ residual with x) -> x1
    tgemm<true><<<gP, blk, SMEM_G>>>(a16, pw16, proj_b, x, x1, T_TOK, DMODEL, DMODEL);
    // #10: norm2 -> fp16
    ln16<DMODEL><<<T_TOK, blk>>>(x1, n2g, n2b, a16);
    // #11: fused FFN up projection (w1|w2)
    tgemm<false><<<gW12, blk, SMEM_G>>>(a16, w1216, w12b, nullptr, h12, T_TOK, 2 * HDIM, DMODEL);
    // #12: silu(x1h)*x2h -> ffn LN -> fp16
    silu_ln16<<<T_TOK, blk>>>(h12, fg, fb, h16);
    // #13: down projection + residual -> out
    tgemm<true><<<gP, blk, SMEM_G>>>(h16, w316, w3b, x1, out, T_TOK, DMODEL, HDIM);
}

// round 13
// speedup vs baseline: 1.3992x; 1.2726x over previous
#include <cuda_runtime.h>
#include <cuda_fp16.h>
#include <stdint.h>
#include <math.h>

#define NTOK   257
#define BATCH  64
#define T_TOK  (BATCH * NTOK)   // 16448
#define DMODEL 1024
#define NHEAD  16
#define HD     64
#define HDIM   4096
#define LN_EPS 1e-5f
#define STRQ   3072              // fused qkv row stride

// ---------------- scratch (device globals; no allocations allowed) ----------
__device__ __align__(16) float g_qkv[(size_t)T_TOK * STRQ];
__device__ __align__(16) float g_att[(size_t)T_TOK * DMODEL];
__device__ __align__(16) float g_x1 [(size_t)T_TOK * DMODEL];
__device__ __align__(16) float g_h12[(size_t)T_TOK * 2 * HDIM];

__device__ __align__(16) __half g_a16[(size_t)T_TOK * DMODEL];
__device__ __align__(16) __half g_h16[(size_t)T_TOK * HDIM];
__device__ __align__(16) __half g_qkvw16[(size_t)3 * DMODEL * DMODEL];
__device__ __align__(16) __half g_pw16[(size_t)DMODEL * DMODEL];
__device__ __align__(16) __half g_w1216[(size_t)2 * HDIM * DMODEL];
__device__ __align__(16) __half g_w316[(size_t)DMODEL * HDIM];
__device__ __align__(16) float  g_qkvb[3 * DMODEL];
__device__ __align__(16) float  g_w12b[2 * HDIM];

// ---------------- fp32 -> fp16 helpers --------------------------------------
__device__ __forceinline__ uint2 pack16(float4 t)
{
    __half2 a = __floats2half2_rn(t.x, t.y);
    __half2 b = __floats2half2_rn(t.z, t.w);
    uint2 r;
    r.x = *(uint32_t*)&a;
    r.y = *(uint32_t*)&b;
    return r;
}

__global__ void __launch_bounds__(256) cvt4(const float* __restrict__ s0, __half* __restrict__ d0,
                                            const float* __restrict__ s1, __half* __restrict__ d1,
                                            const float* __restrict__ s2, __half* __restrict__ d2,
                                            const float* __restrict__ s3, __half* __restrict__ d3,
                                            int n4)
{
    int i = blockIdx.x * 256 + threadIdx.x;
    if (i >= n4) return;
    const float* s = (blockIdx.y == 0) ? s0 : (blockIdx.y == 1) ? s1 : (blockIdx.y == 2) ? s2 : s3;
    __half*      d = (blockIdx.y == 0) ? d0 : (blockIdx.y == 1) ? d1 : (blockIdx.y == 2) ? d2 : d3;
    ((uint2*)d)[i] = pack16(((const float4*)s)[i]);
}

__global__ void __launch_bounds__(256) pack_biases(const float* __restrict__ qb,
                                                   const float* __restrict__ vb,
                                                   const float* __restrict__ b1,
                                                   const float* __restrict__ b2,
                                                   float* __restrict__ qkvb,
                                                   float* __restrict__ w12b)
{
    int i = blockIdx.x * 256 + threadIdx.x;
    if (i < 3 * DMODEL) {
        qkvb[i] = (i < DMODEL) ? qb[i] : ((i < 2 * DMODEL) ? 0.f : vb[i - 2 * DMODEL]);
    } else {
        int j = i - 3 * DMODEL;
        if (j < 2 * HDIM) w12b[j] = (j < HDIM) ? b1[j] : b2[j - HDIM];
    }
}

// ---------------- mma.sync GEMM (unchanged from R12) -------------------------
#define RSB    80
#define APLANE (128 * RSB)
#define BPLANE (128 * RSB)
#define STAGE  (APLANE + BPLANE)
#define NSTAGE 3
#define SMEM_G (NSTAGE * STAGE)

#define LDSM4(r0, r1, r2, r3, addr) \
    asm volatile("ldmatrix.sync.aligned.m8n8.x4.shared.b16 {%0,%1,%2,%3}, [%4];" \
                 : "=r"(r0), "=r"(r1), "=r"(r2), "=r"(r3) : "r"(addr))

#define MMA16816(c, a, b) \
    asm volatile("mma.sync.aligned.m16n8k16.row.col.f32.f16.f16.f32 " \
                 "{%0,%1,%2,%3}, {%4,%5,%6,%7}, {%8,%9}, {%0,%1,%2,%3};" \
                 : "+f"((c)[0]), "+f"((c)[1]), "+f"((c)[2]), "+f"((c)[3]) \
                 : "r"((a)[0]), "r"((a)[1]), "r"((a)[2]), "r"((a)[3]), \
                   "r"((b)[0]), "r"((b)[1]))

#define MMAF(c, a0_, a1_, a2_, a3_, b0_, b1_) \
    asm volatile("mma.sync.aligned.m16n8k16.row.col.f32.f16.f16.f32 " \
                 "{%0,%1,%2,%3}, {%4,%5,%6,%7}, {%8,%9}, {%0,%1,%2,%3};" \
                 : "+f"((c)[0]), "+f"((c)[1]), "+f"((c)[2]), "+f"((c)[3]) \
                 : "r"(a0_), "r"(a1_), "r"(a2_), "r"(a3_), "r"(b0_), "r"(b1_))

template<bool RES>
__global__ void __launch_bounds__(256, 2) tgemm(const __half* __restrict__ A,
                                                const __half* __restrict__ B,
                                                const float* __restrict__ bias,
                                                const float* __restrict__ res,
                                                float* __restrict__ C,
                                                int M, int N, int K)
{
    extern __shared__ __align__(16) char dsm[];
    uint32_t sb = (uint32_t)__cvta_generic_to_shared(dsm);

    int tid = threadIdx.x, lane = tid & 31, warp = tid >> 5;
    int wm = warp >> 2, wn = warp & 3;
    int m0 = blockIdx.y * 128, n0 = blockIdx.x * 128;

    float acc[4][4][4];
#pragma unroll
    for (int i = 0; i < 4; i++)
#pragma unroll
        for (int j = 0; j < 4; j++)
#pragma unroll
            for (int r = 0; r < 4; r++) acc[i][j][r] = 0.f;

    auto issue_loads = [&](int c) {
        int k0 = c * 32;
        uint32_t sbuf = sb + (uint32_t)(c % NSTAGE) * STAGE;
#pragma unroll
        for (int i = 0; i < 4; i++) {
            int gi = i * 256 + tid;
            int p = gi >> 9;
            int idx = gi & 511;
            int row = idx >> 2, cc = idx & 3;
            if (p == 0) {
                int grow = m0 + row;
                int sz = 16;
                if (grow >= M) { grow = 0; sz = 0; }
                const void* src = A + (size_t)grow * K + k0 + cc * 8;
                uint32_t dst = sbuf + (uint32_t)(row * RSB + cc * 16);
                asm volatile("cp.async.ca.shared.global [%0], [%1], 16, %2;"
                             :: "r"(dst), "l"(src), "r"(sz));
            } else {
                const void* src = B + (size_t)(n0 + row) * K + k0 + cc * 8;
                uint32_t dst = sbuf + APLANE + (uint32_t)(row * RSB + cc * 16);
                asm volatile("cp.async.cg.shared.global [%0], [%1], 16;"
                             :: "r"(dst), "l"(src));
            }
        }
        asm volatile("cp.async.commit_group;" ::: "memory");
    };

    int KT = K >> 5;
    issue_loads(0);
    issue_loads(1);
    asm volatile("cp.async.wait_group 1;" ::: "memory");
    __syncthreads();

    for (int c = 0; c < KT; c++) {
        uint32_t sbuf = sb + (uint32_t)(c % NSTAGE) * STAGE;
        if (c + 2 < KT) issue_loads(c + 2);

#pragma unroll
        for (int kk = 0; kk < 32; kk += 16) {
            uint32_t af[4][4], bf[4][2];
#pragma unroll
            for (int mi = 0; mi < 4; mi++) {
                int arow = wm * 64 + mi * 16 + (lane & 15);
                uint32_t aoff = (uint32_t)(arow * RSB + (kk + (lane >> 4) * 8) * 2);
                LDSM4(af[mi][0], af[mi][1], af[mi][2], af[mi][3], sbuf + aoff);
            }
#pragma unroll
            for (int nj = 0; nj < 2; nj++) {
                int g = lane >> 3;
                int nrow = wn * 32 + nj * 16 + (g >> 1) * 8 + (lane & 7);
                uint32_t boff = (uint32_t)(nrow * RSB + (kk + (g & 1) * 8) * 2);
                LDSM4(bf[nj*2][0], bf[nj*2][1], bf[nj*2+1][0], bf[nj*2+1][1],
                      sbuf + APLANE + boff);
            }
#pragma unroll
            for (int mi = 0; mi < 4; mi++)
#pragma unroll
                for (int ni = 0; ni < 4; ni++)
                    MMA16816(acc[mi][ni], af[mi], bf[ni]);
        }

        if (c + 1 < KT) {
            asm volatile("cp.async.wait_group 1;" ::: "memory");
            __syncthreads();
        }
    }

#pragma unroll
    for (int mi = 0; mi < 4; mi++) {
#pragma unroll
        for (int ni = 0; ni < 4; ni++) {
            int r0 = m0 + wm * 64 + mi * 16 + (lane >> 2);
            int col = n0 + wn * 32 + ni * 8 + (lane & 3) * 2;
            float bx = 0.f, by = 0.f;
            if (bias) { bx = bias[col]; by = bias[col + 1]; }
            float2 v0, v1;
            v0.x = acc[mi][ni][0] + bx; v0.y = acc[mi][ni][1] + by;
            v1.x = acc[mi][ni][2] + bx; v1.y = acc[mi][ni][3] + by;
            if (r0 < M) {
                size_t off = (size_t)r0 * N + col;
                if (RES) { float2 rr = *(const float2*)&res[off]; v0.x += rr.x; v0.y += rr.y; }
                *(float2*)&C[off] = v0;
            }
            if (r0 + 8 < M) {
                size_t off = (size_t)(r0 + 8) * N + col;
                if (RES) { float2 rr = *(const float2*)&res[off]; v1.x += rr.x; v1.y += rr.y; }
                *(float2*)&C[off] = v1;
            }
        }
    }
}

// ---------------- LayerNorm -> fp16 plane ------------------------------------
template<int W>
__global__ void __launch_bounds__(256) ln16(const float* __restrict__ x,
                                            const float* __restrict__ g,
                                            const float* __restrict__ b,
                                            __half* __restrict__ o16)
{
    constexpr int V = W / 1024;
    __shared__ float red0[8], red1[8];
    __shared__ float stats[2];
    size_t rb = (size_t)blockIdx.x * W;
    const float4* xr = (const float4*)(x + rb);
    float4 vv[V];
    float s = 0.f, s2 = 0.f;
#pragma unroll
    for (int i = 0; i < V; i++) {
        float4 t = xr[threadIdx.x + i * 256];
        vv[i] = t;
        s  += t.x + t.y + t.z + t.w;
        s2 += t.x*t.x + t.y*t.y + t.z*t.z + t.w*t.w;
    }
#pragma unroll
    for (int o = 16; o; o >>= 1) {
        s  += __shfl_xor_sync(0xffffffffu, s,  o);
        s2 += __shfl_xor_sync(0xffffffffu, s2, o);
    }
    if ((threadIdx.x & 31) == 0) { red0[threadIdx.x >> 5] = s; red1[threadIdx.x >> 5] = s2; }
    __syncthreads();
    if (threadIdx.x == 0) {
        float a = 0.f, c = 0.f;
#pragma unroll
        for (int i = 0; i < 8; i++) { a += red0[i]; c += red1[i]; }
        float mu  = a / (float)W;
        float var = c / (float)W - mu * mu;
        stats[0] = mu;
        stats[1] = rsqrtf(var + LN_EPS);
    }
    __syncthreads();
    float mu = stats[0], inv = stats[1];
    const float4* g4 = (const float4*)g;
    const float4* b4 = (const float4*)b;
#pragma unroll
    for (int i = 0; i < V; i++) {
        int c = threadIdx.x + i * 256;
        float4 gg = g4[c], bb = b4[c], t = vv[i], o;
        o.x = (t.x - mu) * inv * gg.x + bb.x;
        o.y = (t.y - mu) * inv * gg.y + bb.y;
        o.z = (t.z - mu) * inv * gg.z + bb.z;
        o.w = (t.w - mu) * inv * gg.w + bb.w;
        ((uint2*)(o16 + rb))[c] = pack16(o);
    }
}

// ---------------- fused SiLU(x1)*x2 -> LayerNorm -> fp16 ---------------------
__global__ void __launch_bounds__(256) silu_ln16(const float* __restrict__ h12,
                                                 const float* __restrict__ g,
                                                 const float* __restrict__ b,
                                                 __half* __restrict__ o16)
{
    constexpr int W = HDIM;
    constexpr int V = W / 1024;
    __shared__ float red0[8], red1[8];
    __shared__ float stats[2];
    size_t rb12 = (size_t)blockIdx.x * (2 * HDIM);
    size_t rb   = (size_t)blockIdx.x * W;
    const float4* ar = (const float4*)(h12 + rb12);
    const float4* cr = (const float4*)(h12 + rb12 + HDIM);
    float4 vv[V];
    float s = 0.f, s2 = 0.f;
#pragma unroll
    for (int i = 0; i < V; i++) {
        float4 a = ar[threadIdx.x + i * 256];
        float4 c = cr[threadIdx.x + i * 256];
        float4 t;
        t.x = a.x / (1.f + __expf(-a.x)) * c.x;
        t.y = a.y / (1.f + __expf(-a.y)) * c.y;
        t.z = a.z / (1.f + __expf(-a.z)) * c.z;
        t.w = a.w / (1.f + __expf(-a.w)) * c.w;
        vv[i] = t;
        s  += t.x + t.y + t.z + t.w;
        s2 += t.x*t.x + t.y*t.y + t.z*t.z + t.w*t.w;
    }
#pragma unroll
    for (int o = 16; o; o >>= 1) {
        s  += __shfl_xor_sync(0xffffffffu, s,  o);
        s2 += __shfl_xor_sync(0xffffffffu, s2, o);
    }
    if ((threadIdx.x & 31) == 0) { red0[threadIdx.x >> 5] = s; red1[threadIdx.x >> 5] = s2; }
    __syncthreads();
    if (threadIdx.x == 0) {
        float a = 0.f, c = 0.f;
#pragma unroll
        for (int i = 0; i < 8; i++) { a += red0[i]; c += red1[i]; }
        float mu  = a / (float)W;
        float var = c / (float)W - mu * mu;
        stats[0] = mu;
        stats[1] = rsqrtf(var + LN_EPS);
    }
    __syncthreads();
    float mu = stats[0], inv = stats[1];
    const float4* g4 = (const float4*)g;
    const float4* b4 = (const float4*)b;
#pragma unroll
    for (int i = 0; i < V; i++) {
        int c = threadIdx.x + i * 256;
        float4 gg = g4[c], bb = b4[c], t = vv[i], o;
        o.x = (t.x - mu) * inv * gg.x + bb.x;
        o.y = (t.y - mu) * inv * gg.y + bb.y;
        o.z = (t.z - mu) * inv * gg.z + bb.z;
        o.w = (t.w - mu) * inv * gg.w + bb.w;
        ((uint2*)(o16 + rb))[c] = pack16(o);
    }
}

// ---------------- RoPE on q,k in fused qkv buffer; scale q ------------------
__global__ void __launch_bounds__(256) rope_kernel(float* __restrict__ qkv,
                                                   const float* __restrict__ cosb,
                                                   const float* __restrict__ sinb)
{
    const float scale = 0.125f;
    int row = blockIdx.x;
    int n = row % NTOK;
    float4* qr = (float4*)(qkv + (size_t)row * STRQ);
    float4* kr = (float4*)(qkv + (size_t)row * STRQ + DMODEL);
    int ci = threadIdx.x;
    if (n == 0) {
        float4 t = qr[ci];
        t.x *= scale; t.y *= scale; t.z *= scale; t.w *= scale;
        qr[ci] = t;
        return;
    }
    int d = (ci * 4) & 63;
    const float4 cs = *(const float4*)(cosb + (size_t)(n - 1) * HD + d);
    const float4 sn = *(const float4*)(sinb + (size_t)(n - 1) * HD + d);
    float4 t = qr[ci], o;
    o.x = t.x * cs.x - t.y * sn.x;
    o.y = t.y * cs.y + t.x * sn.y;
    o.z = t.z * cs.z - t.w * sn.z;
    o.w = t.w * cs.w + t.z * sn.w;
    o.x *= scale; o.y *= scale; o.z *= scale; o.w *= scale;
    qr[ci] = o;
    t = kr[ci];
    o.x = t.x * cs.x - t.y * sn.x;
    o.y = t.y * cs.y + t.x * sn.y;
    o.z = t.z * cs.z - t.w * sn.z;
    o.w = t.w * cs.w + t.z * sn.w;
    kr[ci] = o;
}

// ---------------- attention v4: tensor-core, register-resident P ------------
// Padded tokens: 272. smem (halves): Qh,Ql,Kh,Kl [272][72]; Vt [64][280]; bias fp32.
#define QSTRH 72
#define VSTRH 280
#define HOFF_QH 0
#define HOFF_QL (HOFF_QH + 272 * QSTRH)
#define HOFF_KH (HOFF_QL + 272 * QSTRH)
#define HOFF_KL (HOFF_KH + 272 * QSTRH)
#define HOFF_VT (HOFF_KL + 272 * QSTRH)
#define HOFF_END (HOFF_VT + 64 * VSTRH)
#define ATTN_SMEM_BYTES (HOFF_END * 2 + 964 * 4)

__global__ void __launch_bounds__(256) attn_kernel(const float* __restrict__ qkv,
                                                   const float* __restrict__ table,
                                                   float* __restrict__ out)
{
    extern __shared__ __align__(16) __half smh[];
    __half* Qh = smh + HOFF_QH;
    __half* Ql = smh + HOFF_QL;
    __half* Kh = smh + HOFF_KH;
    __half* Kl = smh + HOFF_KL;
    __half* Vt = smh + HOFF_VT;
    float*  bsf = (float*)(smh + HOFF_END);

    int bh = blockIdx.x;
    int b = bh >> 4, h = bh & 15;
    int tid = threadIdx.x, lane = tid & 31, w = tid >> 5;
    const float* qg = qkv + (size_t)b * NTOK * STRQ + h * HD;
    const float* kg = qg + DMODEL;
    const float* vg = qg + 2 * DMODEL;

    // load Q,K hi/lo planes (coalesced)
    for (int i = tid; i < 272 * 64; i += 256) {
        int r = i >> 6, c = i & 63;
        float qv = 0.f, kv = 0.f;
        if (r < NTOK) {
            qv = qg[(size_t)r * STRQ + c];
            kv = kg[(size_t)r * STRQ + c];
        }
        __half qh_ = __float2half_rn(qv);
        __half kh_ = __float2half_rn(kv);
        Qh[r * QSTRH + c] = qh_;
        Ql[r * QSTRH + c] = __float2half_rn(qv - __half2float(qh_));
        Kh[r * QSTRH + c] = kh_;
        Kl[r * QSTRH + c] = __float2half_rn(kv - __half2float(kh_));
    }
    // load V transposed (coalesced gmem: consecutive threads -> consecutive d)
    for (int i = tid; i < 64 * 272; i += 256) {
        int d = i & 63, kk = i >> 6;
        float v = (kk < NTOK) ? vg[(size_t)kk * STRQ + d] : 0.f;
        Vt[d * VSTRH + kk] = __float2half_rn(v);
    }
    for (int i = tid; i < 964; i += 256) bsf[i] = table[(size_t)i * NHEAD + h];
    __syncthreads();

    uint32_t base = (uint32_t)__cvta_generic_to_shared(smh);
    int r0 = lane >> 2;
    int cb = (lane & 3) * 2;
    int g = lane >> 3;

    for (int t = w; t < 17; t += 8) {
        int m0 = t * 16;
        // Q A-fragments for 4 k-steps, hi and lo
        uint32_t qfh[4][4], qfl[4][4];
#pragma unroll
        for (int ks = 0; ks < 4; ks++) {
            uint32_t off = (uint32_t)((m0 + (lane & 15)) * QSTRH + ks * 16 + (lane >> 4) * 8) * 2;
            LDSM4(qfh[ks][0], qfh[ks][1], qfh[ks][2], qfh[ks][3], base + HOFF_QH * 2 + off);
            LDSM4(qfl[ks][0], qfl[ks][1], qfl[ks][2], qfl[ks][3], base + HOFF_QL * 2 + off);
        }

        float sacc[34][4];
#pragma unroll
        for (int nt = 0; nt < 34; nt++)
#pragma unroll
            for (int r = 0; r < 4; r++) sacc[nt][r] = 0.f;

        // S = Qh*Kh + Ql*Kh + Qh*Kl   (keys = rows of Kh/Kl)
#pragma unroll
        for (int np = 0; np < 17; np++) {
#pragma unroll
            for (int ks = 0; ks < 4; ks++) {
                uint32_t roff = (uint32_t)((np * 16 + (g >> 1) * 8 + (lane & 7)) * QSTRH
                                           + ks * 16 + (g & 1) * 8) * 2;
                uint32_t bh0, bh1, bh2, bh3, bl0, bl1, bl2, bl3;
                LDSM4(bh0, bh1, bh2, bh3, base + HOFF_KH * 2 + roff);
                LDSM4(bl0, bl1, bl2, bl3, base + HOFF_KL * 2 + roff);
                MMAF(sacc[2*np],   qfh[ks][0], qfh[ks][1], qfh[ks][2], qfh[ks][3], bh0, bh1);
                MMAF(sacc[2*np+1], qfh[ks][0], qfh[ks][1], qfh[ks][2], qfh[ks][3], bh2, bh3);
                MMAF(sacc[2*np],   qfl[ks][0], qfl[ks][1], qfl[ks][2], qfl[ks][3], bh0, bh1);
                MMAF(sacc[2*np+1], qfl[ks][0], qfl[ks][1], qfl[ks][2], qfl[ks][3], bh2, bh3);
                MMAF(sacc[2*np],   qfh[ks][0], qfh[ks][1], qfh[ks][2], qfh[ks][3], bl0, bl1);
                MMAF(sacc[2*np+1], qfh[ks][0], qfh[ks][1], qfh[ks][2], qfh[ks][3], bl2, bl3);
            }
        }

        // bias + masking + softmax (rows q0g, q1g)
        int q0g = m0 + r0, q1g = q0g + 8;
        int q0e = (q0g < 256) ? q0g : 256;
        int q1e = (q1g < 256) ? q1g : 256;
        int Cq0 = (q0e >= 1) ? (((q0e - 1) >> 4) * 31 + ((q0e - 1) & 15) + 480) : 0;
        int Cq1 = (q1e >= 1) ? (((q1e - 1) >> 4) * 31 + ((q1e - 1) & 15) + 480) : 0;

#pragma unroll
        for (int nt = 0; nt < 34; nt++) {
#pragma unroll
            for (int r = 0; r < 4; r++) {
                int col = nt * 8 + cb + (r & 1);
                int qe = (r < 2) ? q0e : q1e;
                int Cq = (r < 2) ? Cq0 : Cq1;
                if (col >= NTOK) { sacc[nt][r] = -1e30f; }
                else {
                    int idx;
                    if (qe == 0)        idx = (col == 0) ? 963 : 961;
                    else if (col == 0)  idx = 962;
                    else                idx = Cq - (((col - 1) >> 4) * 31 + ((col - 1) & 15));
                    sacc[nt][r] += bsf[idx];
                }
            }
        }
        float mx0 = -1e30f, mx1 = -1e30f;
#pragma unroll
        for (int nt = 0; nt < 34; nt++) {
            mx0 = fmaxf(mx0, fmaxf(sacc[nt][0], sacc[nt][1]));
            mx1 = fmaxf(mx1, fmaxf(sacc[nt][2], sacc[nt][3]));
        }
        mx0 = fmaxf(mx0, __shfl_xor_sync(0xffffffffu, mx0, 1));
        mx0 = fmaxf(mx0, __shfl_xor_sync(0xffffffffu, mx0, 2));
        mx1 = fmaxf(mx1, __shfl_xor_sync(0xffffffffu, mx1, 1));
        mx1 = fmaxf(mx1, __shfl_xor_sync(0xffffffffu, mx1, 2));
        float sum0 = 0.f, sum1 = 0.f;
#pragma unroll
        for (int nt = 0; nt < 34; nt++) {
            sacc[nt][0] = __expf(sacc[nt][0] - mx0);
            sacc[nt][1] = __expf(sacc[nt][1] - mx0);
            sacc[nt][2] = __expf(sacc[nt][2] - mx1);
            sacc[nt][3] = __expf(sacc[nt][3] - mx1);
            sum0 += sacc[nt][0] + sacc[nt][1];
            sum1 += sacc[nt][2] + sacc[nt][3];
        }
        sum0 += __shfl_xor_sync(0xffffffffu, sum0, 1);
        sum0 += __shfl_xor_sync(0xffffffffu, sum0, 2);
        sum1 += __shfl_xor_sync(0xffffffffu, sum1, 1);
        sum1 += __shfl_xor_sync(0xffffffffu, sum1, 2);
        float inv0 = 1.f / sum0, inv1 = 1.f / sum1;
#pragma unroll
        for (int nt = 0; nt < 34; nt++) {
            sacc[nt][0] *= inv0; sacc[nt][1] *= inv0;
            sacc[nt][2] *= inv1; sacc[nt][3] *= inv1;
        }

        // O = P * V  (P packed from sacc into A-fragments)
        float oacc[8][4];
#pragma unroll
        for (int dt = 0; dt < 8; dt++)
#pragma unroll
            for (int r = 0; r < 4; r++) oacc[dt][r] = 0.f;

#pragma unroll
        for (int j = 0; j < 17; j++) {
            uint32_t pa0, pa1, pa2, pa3;
            { __half2 tt = __floats2half2_rn(sacc[2*j][0],   sacc[2*j][1]);   pa0 = *(uint32_t*)&tt; }
            { __half2 tt = __floats2half2_rn(sacc[2*j][2],   sacc[2*j][3]);   pa1 = *(uint32_t*)&tt; }
            { __half2 tt = __floats2half2_rn(sacc[2*j+1][0], sacc[2*j+1][1]); pa2 = *(uint32_t*)&tt; }
            { __half2 tt = __floats2half2_rn(sacc[2*j+1][2], sacc[2*j+1][3]); pa3 = *(uint32_t*)&tt; }
#pragma unroll
            for (int dp = 0; dp < 4; dp++) {
                uint32_t roff = (uint32_t)((dp * 16 + (g >> 1) * 8 + (lane & 7)) * VSTRH
                                           + j * 16 + (g & 1) * 8) * 2;
                uint32_t vb0, vb1, vb2, vb3;
                LDSM4(vb0, vb1, vb2, vb3, base + HOFF_VT * 2 + roff);
                MMAF(oacc[2*dp],   pa0, pa1, pa2, pa3, vb0, vb1);
                MMAF(oacc[2*dp+1], pa0, pa1, pa2, pa3, vb2, vb3);
            }
        }

        // store O rows q0g / q1g
#pragma unroll
        for (int dt = 0; dt < 8; dt++) {
            if (q0g < NTOK) {
                float2 o2; o2.x = oacc[dt][0]; o2.y = oacc[dt][1];
                *(float2*)&out[((size_t)b * NTOK + q0g) * DMODEL + h * HD + dt * 8 + cb] = o2;
            }
            if (q1g < NTOK) {
                float2 o2; o2.x = oacc[dt][2]; o2.y = oacc[dt][3];
                *(float2*)&out[((size_t)b * NTOK + q1g) * DMODEL + h * HD + dt * 8 + cb] = o2;
            }
        }
    }
}

// ---------------- launch -----------------------------------------------------
extern "C" void kernel_launch(void* const* d_in, const int* in_sizes, int n_in,
                              void* d_out, int out_size)
{
    const float* x        = (const float*)d_in[0];
    const float* rope_cos = (const float*)d_in[1];
    const float* rope_sin = (const float*)d_in[2];
    const float* q_w      = (const float*)d_in[3];
    const float* q_b      = (const float*)d_in[4];
    const float* k_w      = (const float*)d_in[5];
    const float* v_w      = (const float*)d_in[6];
    const float* v_b      = (const float*)d_in[7];
    const float* table    = (const float*)d_in[8];
    const float* in_g     = (const float*)d_in[9];
    const float* in_b     = (const float*)d_in[10];
    const float* proj_w   = (const float*)d_in[11];
    const float* proj_b   = (const float*)d_in[12];
    const float* n1g      = (const float*)d_in[13];
    const float* n1b      = (const float*)d_in[14];
    const float* n2g      = (const float*)d_in[15];
    const float* n2b      = (const float*)d_in[16];
    const float* w1       = (const float*)d_in[17];
    const float* w1b      = (const float*)d_in[18];
    const float* w2       = (const float*)d_in[19];
    const float* w2b      = (const float*)d_in[20];
    const float* fg       = (const float*)d_in[21];
    const float* fb       = (const float*)d_in[22];
    const float* w3       = (const float*)d_in[23];
    const float* w3b      = (const float*)d_in[24];
    float* out = (float*)d_out;

    float *qkv, *att, *x1, *h12, *qkvb, *w12b;
    __half *a16, *h16, *qkvw16, *pw16, *w1216, *w316;
    cudaGetSymbolAddress((void**)&qkv,    g_qkv);
    cudaGetSymbolAddress((void**)&att,    g_att);
    cudaGetSymbolAddress((void**)&x1,     g_x1);
    cudaGetSymbolAddress((void**)&h12,    g_h12);
    cudaGetSymbolAddress((void**)&a16,    g_a16);
    cudaGetSymbolAddress((void**)&h16,    g_h16);
    cudaGetSymbolAddress((void**)&qkvw16, g_qkvw16);
    cudaGetSymbolAddress((void**)&pw16,   g_pw16);
    cudaGetSymbolAddress((void**)&w1216,  g_w1216);
    cudaGetSymbolAddress((void**)&w316,   g_w316);
    cudaGetSymbolAddress((void**)&qkvb,   g_qkvb);
    cudaGetSymbolAddress((void**)&w12b,   g_w12b);

    cudaFuncSetAttribute(attn_kernel, cudaFuncAttributeMaxDynamicSharedMemorySize, ATTN_SMEM_BYTES);
    cudaFuncSetAttribute(tgemm<false>, cudaFuncAttributeMaxDynamicSharedMemorySize, SMEM_G);
    cudaFuncSetAttribute(tgemm<true>,  cudaFuncAttributeMaxDynamicSharedMemorySize, SMEM_G);

    dim3 blk(256);
    dim3 gQKV(3 * DMODEL / 128, (T_TOK + 127) / 128);   // (24, 129)
    dim3 gP(DMODEL / 128,       (T_TOK + 127) / 128);   // (8, 129)
    dim3 gW12(2 * HDIM / 128,   (T_TOK + 127) / 128);   // (64, 129)

    const int n4_1M = DMODEL * DMODEL / 4;
    const int n4_4M = HDIM * DMODEL / 4;

    // #1: convert q/k/v/proj weights
    cvt4<<<dim3((n4_1M + 255) / 256, 4), blk>>>(
        q_w, qkvw16,
        k_w, qkvw16 + (size_t)DMODEL * DMODEL,
        v_w, qkvw16 + (size_t)2 * DMODEL * DMODEL,
        proj_w, pw16, n4_1M);
    // #2: pack biases
    pack_biases<<<(3 * DMODEL + 2 * HDIM + 255) / 256, blk>>>(q_b, v_b, w1b, w2b, qkvb, w12b);
    // #3: norm1 -> fp16
    ln16<DMODEL><<<T_TOK, blk>>>(x, n1g, n1b, a16);
    // #4: fused QKV projection
    tgemm<false><<<gQKV, blk, SMEM_G>>>(a16, qkvw16, qkvb, nullptr, qkv, T_TOK, 3 * DMODEL, DMODEL);
    // #5: RoPE + q scaling
    rope_kernel<<<T_TOK, blk>>>(qkv, rope_cos, rope_sin);
    // #6: attention (tensor cores)
    attn_kernel<<<BATCH * NHEAD, blk, ATTN_SMEM_BYTES>>>(qkv, table, att);
    // #7: convert FFN weights
    cvt4<<<dim3((n4_4M + 255) / 256, 3), blk>>>(
        w1, w1216,
        w2, w1216 + (size_t)HDIM * DMODEL,
        w3, w316,
        w3, w316, n4_4M);
    // #8: inner LN -> fp16
    ln16<DMODEL><<<T_TOK, blk>>>(att, in_g, in_b, a16);
    // #9: proj (+ residual with x) -> x1
    tgemm<true><<<gP, blk, SMEM_G>>>(a16, pw16, proj_b, x, x1, T_TOK, DMODEL, DMODEL);
    // #10: norm2 -> fp16
    ln16<DMODEL><<<T_TOK, blk>>>(x1, n2g, n2b, a16);
    // #11: fused FFN up projection (w1|w2)
    tgemm<false><<<gW12, blk, SMEM_G>>>(a16, w1216, w12b, nullptr, h12, T_TOK, 2 * HDIM, DMODEL);
    // #12: silu(x1h)*x2h -> ffn LN -> fp16
    silu_ln16<<<T_TOK, blk>>>(h12, fg, fb, h16);
    // #13: down projection + residual -> out
    tgemm<true><<<gP, blk, SMEM_G>>>(h16, w316, w3b, x1, out, T_TOK, DMODEL, HDIM);
}

// round 15
// speedup vs baseline: 1.5111x; 1.0800x over previous
#include <cuda_runtime.h>
#include <cuda_fp16.h>
#include <stdint.h>
#include <math.h>

#define NTOK   257
#define BATCH  64
#define T_TOK  (BATCH * NTOK)   // 16448
#define DMODEL 1024
#define NHEAD  16
#define HD     64
#define HDIM   4096
#define LN_EPS 1e-5f
#define STRQ   3072              // fused qkv row stride

// ---------------- scratch (device globals; no allocations allowed) ----------
__device__ __align__(16) float g_qkv[(size_t)T_TOK * STRQ];
__device__ __align__(16) float g_att[(size_t)T_TOK * DMODEL];
__device__ __align__(16) float g_x1 [(size_t)T_TOK * DMODEL];
__device__ __align__(16) float g_h12[(size_t)T_TOK * 2 * HDIM];

__device__ __align__(16) __half g_a16[(size_t)T_TOK * DMODEL];
__device__ __align__(16) __half g_h16[(size_t)T_TOK * HDIM];
__device__ __align__(16) __half g_qkvw16[(size_t)3 * DMODEL * DMODEL];
__device__ __align__(16) __half g_pw16[(size_t)DMODEL * DMODEL];
__device__ __align__(16) __half g_w1216[(size_t)2 * HDIM * DMODEL];
__device__ __align__(16) __half g_w316[(size_t)DMODEL * HDIM];
__device__ __align__(16) float  g_qkvb[3 * DMODEL];
__device__ __align__(16) float  g_w12b[2 * HDIM];

// ---------------- fp32 -> fp16 helpers --------------------------------------
__device__ __forceinline__ uint2 pack16(float4 t)
{
    __half2 a = __floats2half2_rn(t.x, t.y);
    __half2 b = __floats2half2_rn(t.z, t.w);
    uint2 r;
    r.x = *(uint32_t*)&a;
    r.y = *(uint32_t*)&b;
    return r;
}

__global__ void __launch_bounds__(256) cvt4(const float* __restrict__ s0, __half* __restrict__ d0,
                                            const float* __restrict__ s1, __half* __restrict__ d1,
                                            const float* __restrict__ s2, __half* __restrict__ d2,
                                            const float* __restrict__ s3, __half* __restrict__ d3,
                                            int n4)
{
    int i = blockIdx.x * 256 + threadIdx.x;
    if (i >= n4) return;
    const float* s = (blockIdx.y == 0) ? s0 : (blockIdx.y == 1) ? s1 : (blockIdx.y == 2) ? s2 : s3;
    __half*      d = (blockIdx.y == 0) ? d0 : (blockIdx.y == 1) ? d1 : (blockIdx.y == 2) ? d2 : d3;
    ((uint2*)d)[i] = pack16(((const float4*)s)[i]);
}

__global__ void __launch_bounds__(256) pack_biases(const float* __restrict__ qb,
                                                   const float* __restrict__ vb,
                                                   const float* __restrict__ b1,
                                                   const float* __restrict__ b2,
                                                   float* __restrict__ qkvb,
                                                   float* __restrict__ w12b)
{
    int i = blockIdx.x * 256 + threadIdx.x;
    if (i < 3 * DMODEL) {
        qkvb[i] = (i < DMODEL) ? qb[i] : ((i < 2 * DMODEL) ? 0.f : vb[i - 2 * DMODEL]);
    } else {
        int j = i - 3 * DMODEL;
        if (j < 2 * HDIM) w12b[j] = (j < HDIM) ? b1[j] : b2[j - HDIM];
    }
}

// ---------------- mma.sync GEMM v3 ------------------------------------------
// CTA tile 128x128, 4 warps (2x2), warp tile 64x64, 128 threads, K chunk 32,
// 3-stage cp.async pipeline (2 groups in flight, tail-correct wait), 2 CTAs/SM.
#define RSB    80
#define APLANE (128 * RSB)
#define BPLANE (128 * RSB)
#define STAGE  (APLANE + BPLANE)
#define NSTAGE 3
#define SMEM_G (NSTAGE * STAGE)

#define LDSM4(r0, r1, r2, r3, addr) \
    asm volatile("ldmatrix.sync.aligned.m8n8.x4.shared.b16 {%0,%1,%2,%3}, [%4];" \
                 : "=r"(r0), "=r"(r1), "=r"(r2), "=r"(r3) : "r"(addr))

#define MMA16816(c, a, b) \
    asm volatile("mma.sync.aligned.m16n8k16.row.col.f32.f16.f16.f32 " \
                 "{%0,%1,%2,%3}, {%4,%5,%6,%7}, {%8,%9}, {%0,%1,%2,%3};" \
                 : "+f"((c)[0]), "+f"((c)[1]), "+f"((c)[2]), "+f"((c)[3]) \
                 : "r"((a)[0]), "r"((a)[1]), "r"((a)[2]), "r"((a)[3]), \
                   "r"((b)[0]), "r"((b)[1]))

#define MMAF(c, a0_, a1_, a2_, a3_, b0_, b1_) \
    asm volatile("mma.sync.aligned.m16n8k16.row.col.f32.f16.f16.f32 " \
                 "{%0,%1,%2,%3}, {%4,%5,%6,%7}, {%8,%9}, {%0,%1,%2,%3};" \
                 : "+f"((c)[0]), "+f"((c)[1]), "+f"((c)[2]), "+f"((c)[3]) \
                 : "r"(a0_), "r"(a1_), "r"(a2_), "r"(a3_), "r"(b0_), "r"(b1_))

template<bool RES>
__global__ void __launch_bounds__(128, 2) tgemm(const __half* __restrict__ A,
                                                const __half* __restrict__ B,
                                                const float* __restrict__ bias,
                                                const float* __restrict__ res,
                                                float* __restrict__ C,
                                                int M, int N, int K)
{
    extern __shared__ __align__(16) char dsm[];
    uint32_t sb = (uint32_t)__cvta_generic_to_shared(dsm);

    int tid = threadIdx.x, lane = tid & 31, warp = tid >> 5;
    int wm = warp >> 1, wn = warp & 1;           // warp grid 2 x 2
    int m0 = blockIdx.y * 128, n0 = blockIdx.x * 128;

    float acc[4][8][4];
#pragma unroll
    for (int i = 0; i < 4; i++)
#pragma unroll
        for (int j = 0; j < 8; j++)
#pragma unroll
            for (int r = 0; r < 4; r++) acc[i][j][r] = 0.f;

    auto issue_loads = [&](int c) {
        int k0 = c * 32;
        uint32_t sbuf = sb + (uint32_t)(c % NSTAGE) * STAGE;
#pragma unroll
        for (int i = 0; i < 8; i++) {
            int gi = i * 128 + tid;       // 0..1023
            int p = gi >> 9;              // 0:A 1:B
            int idx = gi & 511;
            int row = idx >> 2, cc = idx & 3;
            if (p == 0) {
                int grow = m0 + row;
                int sz = 16;
                if (grow >= M) { grow = 0; sz = 0; }
                const void* src = A + (size_t)grow * K + k0 + cc * 8;
                uint32_t dst = sbuf + (uint32_t)(row * RSB + cc * 16);
                asm volatile("cp.async.ca.shared.global [%0], [%1], 16, %2;"
                             :: "r"(dst), "l"(src), "r"(sz));
            } else {
                const void* src = B + (size_t)(n0 + row) * K + k0 + cc * 8;
                uint32_t dst = sbuf + APLANE + (uint32_t)(row * RSB + cc * 16);
                asm volatile("cp.async.cg.shared.global [%0], [%1], 16;"
                             :: "r"(dst), "l"(src));
            }
        }
        asm volatile("cp.async.commit_group;" ::: "memory");
    };

    int KT = K >> 5;
    issue_loads(0);
    issue_loads(1);
    asm volatile("cp.async.wait_group 1;" ::: "memory");
    __syncthreads();

    for (int c = 0; c < KT; c++) {
        uint32_t sbuf = sb + (uint32_t)(c % NSTAGE) * STAGE;
        if (c + 2 < KT) issue_loads(c + 2);   // 2 groups in flight

#pragma unroll
        for (int kk = 0; kk < 32; kk += 16) {
            uint32_t af[4][4], bf[8][2];
#pragma unroll
            for (int mi = 0; mi < 4; mi++) {
                int arow = wm * 64 + mi * 16 + (lane & 15);
                uint32_t aoff = (uint32_t)(arow * RSB + (kk + (lane >> 4) * 8) * 2);
                LDSM4(af[mi][0], af[mi][1], af[mi][2], af[mi][3], sbuf + aoff);
            }
#pragma unroll
            for (int nj = 0; nj < 4; nj++) {
                int g = lane >> 3;
                int nrow = wn * 64 + nj * 16 + (g >> 1) * 8 + (lane & 7);
                uint32_t boff = (uint32_t)(nrow * RSB + (kk + (g & 1) * 8) * 2);
                LDSM4(bf[nj*2][0], bf[nj*2][1], bf[nj*2+1][0], bf[nj*2+1][1],
                      sbuf + APLANE + boff);
            }
#pragma unroll
            for (int mi = 0; mi < 4; mi++)
#pragma unroll
                for (int ni = 0; ni < 8; ni++)
                    MMA16816(acc[mi][ni], af[mi], bf[ni]);
        }

        if (c + 1 < KT) {
            // tail-correct: when no group was issued this iteration (c+2>=KT),
            // the next stage (c+1) is the LAST pending group -> must wait to 0.
            if (c + 2 < KT) {
                asm volatile("cp.async.wait_group 1;" ::: "memory");
            } else {
                asm volatile("cp.async.wait_group 0;" ::: "memory");
            }
            __syncthreads();
        }
    }

    // epilogue
#pragma unroll
    for (int mi = 0; mi < 4; mi++) {
#pragma unroll
        for (int ni = 0; ni < 8; ni++) {
            int r0 = m0 + wm * 64 + mi * 16 + (lane >> 2);
            int col = n0 + wn * 64 + ni * 8 + (lane & 3) * 2;
            float bx = 0.f, by = 0.f;
            if (bias) { bx = bias[col]; by = bias[col + 1]; }
            float2 v0, v1;
            v0.x = acc[mi][ni][0] + bx; v0.y = acc[mi][ni][1] + by;
            v1.x = acc[mi][ni][2] + bx; v1.y = acc[mi][ni][3] + by;
            if (r0 < M) {
                size_t off = (size_t)r0 * N + col;
                if (RES) { float2 rr = *(const float2*)&res[off]; v0.x += rr.x; v0.y += rr.y; }
                *(float2*)&C[off] = v0;
            }
            if (r0 + 8 < M) {
                size_t off = (size_t)(r0 + 8) * N + col;
                if (RES) { float2 rr = *(const float2*)&res[off]; v1.x += rr.x; v1.y += rr.y; }
                *(float2*)&C[off] = v1;
            }
        }
    }
}

// ---------------- LayerNorm -> fp16 plane ------------------------------------
template<int W>
__global__ void __launch_bounds__(256) ln16(const float* __restrict__ x,
                                            const float* __restrict__ g,
                                            const float* __restrict__ b,
                                            __half* __restrict__ o16)
{
    constexpr int V = W / 1024;
    __shared__ float red0[8], red1[8];
    __shared__ float stats[2];
    size_t rb = (size_t)blockIdx.x * W;
    const float4* xr = (const float4*)(x + rb);
    float4 vv[V];
    float s = 0.f, s2 = 0.f;
#pragma unroll
    for (int i = 0; i < V; i++) {
        float4 t = xr[threadIdx.x + i * 256];
        vv[i] = t;
        s  += t.x + t.y + t.z + t.w;
        s2 += t.x*t.x + t.y*t.y + t.z*t.z + t.w*t.w;
    }
#pragma unroll
    for (int o = 16; o; o >>= 1) {
        s  += __shfl_xor_sync(0xffffffffu, s,  o);
        s2 += __shfl_xor_sync(0xffffffffu, s2, o);
    }
    if ((threadIdx.x & 31) == 0) { red0[threadIdx.x >> 5] = s; red1[threadIdx.x >> 5] = s2; }
    __syncthreads();
    if (threadIdx.x == 0) {
        float a = 0.f, c = 0.f;
#pragma unroll
        for (int i = 0; i < 8; i++) { a += red0[i]; c += red1[i]; }
        float mu  = a / (float)W;
        float var = c / (float)W - mu * mu;
        stats[0] = mu;
        stats[1] = rsqrtf(var + LN_EPS);
    }
    __syncthreads();
    float mu = stats[0], inv = stats[1];
    const float4* g4 = (const float4*)g;
    const float4* b4 = (const float4*)b;
#pragma unroll
    for (int i = 0; i < V; i++) {
        int c = threadIdx.x + i * 256;
        float4 gg = g4[c], bb = b4[c], t = vv[i], o;
        o.x = (t.x - mu) * inv * gg.x + bb.x;
        o.y = (t.y - mu) * inv * gg.y + bb.y;
        o.z = (t.z - mu) * inv * gg.z + bb.z;
        o.w = (t.w - mu) * inv * gg.w + bb.w;
        ((uint2*)(o16 + rb))[c] = pack16(o);
    }
}

// ---------------- fused SiLU(x1)*x2 -> LayerNorm -> fp16 ---------------------
__global__ void __launch_bounds__(256) silu_ln16(const float* __restrict__ h12,
                                                 const float* __restrict__ g,
                                                 const float* __restrict__ b,
                                                 __half* __restrict__ o16)
{
    constexpr int W = HDIM;
    constexpr int V = W / 1024;
    __shared__ float red0[8], red1[8];
    __shared__ float stats[2];
    size_t rb12 = (size_t)blockIdx.x * (2 * HDIM);
    size_t rb   = (size_t)blockIdx.x * W;
    const float4* ar = (const float4*)(h12 + rb12);
    const float4* cr = (const float4*)(h12 + rb12 + HDIM);
    float4 vv[V];
    float s = 0.f, s2 = 0.f;
#pragma unroll
    for (int i = 0; i < V; i++) {
        float4 a = ar[threadIdx.x + i * 256];
        float4 c = cr[threadIdx.x + i * 256];
        float4 t;
        t.x = a.x / (1.f + __expf(-a.x)) * c.x;
        t.y = a.y / (1.f + __expf(-a.y)) * c.y;
        t.z = a.z / (1.f + __expf(-a.z)) * c.z;
        t.w = a.w / (1.f + __expf(-a.w)) * c.w;
        vv[i] = t;
        s  += t.x + t.y + t.z + t.w;
        s2 += t.x*t.x + t.y*t.y + t.z*t.z + t.w*t.w;
    }
#pragma unroll
    for (int o = 16; o; o >>= 1) {
        s  += __shfl_xor_sync(0xffffffffu, s,  o);
        s2 += __shfl_xor_sync(0xffffffffu, s2, o);
    }
    if ((threadIdx.x & 31) == 0) { red0[threadIdx.x >> 5] = s; red1[threadIdx.x >> 5] = s2; }
    __syncthreads();
    if (threadIdx.x == 0) {
        float a = 0.f, c = 0.f;
#pragma unroll
        for (int i = 0; i < 8; i++) { a += red0[i]; c += red1[i]; }
        float mu  = a / (float)W;
        float var = c / (float)W - mu * mu;
        stats[0] = mu;
        stats[1] = rsqrtf(var + LN_EPS);
    }
    __syncthreads();
    float mu = stats[0], inv = stats[1];
    const float4* g4 = (const float4*)g;
    const float4* b4 = (const float4*)b;
#pragma unroll
    for (int i = 0; i < V; i++) {
        int c = threadIdx.x + i * 256;
        float4 gg = g4[c], bb = b4[c], t = vv[i], o;
        o.x = (t.x - mu) * inv * gg.x + bb.x;
        o.y = (t.y - mu) * inv * gg.y + bb.y;
        o.z = (t.z - mu) * inv * gg.z + bb.z;
        o.w = (t.w - mu) * inv * gg.w + bb.w;
        ((uint2*)(o16 + rb))[c] = pack16(o);
    }
}

// ---------------- RoPE on q,k in fused qkv buffer; scale q ------------------
__global__ void __launch_bounds__(256) rope_kernel(float* __restrict__ qkv,
                                                   const float* __restrict__ cosb,
                                                   const float* __restrict__ sinb)
{
    const float scale = 0.125f;
    int row = blockIdx.x;
    int n = row % NTOK;
    float4* qr = (float4*)(qkv + (size_t)row * STRQ);
    float4* kr = (float4*)(qkv + (size_t)row * STRQ + DMODEL);
    int ci = threadIdx.x;
    if (n == 0) {
        float4 t = qr[ci];
        t.x *= scale; t.y *= scale; t.z *= scale; t.w *= scale;
        qr[ci] = t;
        return;
    }
    int d = (ci * 4) & 63;
    const float4 cs = *(const float4*)(cosb + (size_t)(n - 1) * HD + d);
    const float4 sn = *(const float4*)(sinb + (size_t)(n - 1) * HD + d);
    float4 t = qr[ci], o;
    o.x = t.x * cs.x - t.y * sn.x;
    o.y = t.y * cs.y + t.x * sn.y;
    o.z = t.z * cs.z - t.w * sn.z;
    o.w = t.w * cs.w + t.z * sn.w;
    o.x *= scale; o.y *= scale; o.z *= scale; o.w *= scale;
    qr[ci] = o;
    t = kr[ci];
    o.x = t.x * cs.x - t.y * sn.x;
    o.y = t.y * cs.y + t.x * sn.y;
    o.z = t.z * cs.z - t.w * sn.z;
    o.w = t.w * cs.w + t.z * sn.w;
    kr[ci] = o;
}

// ---------------- attention v4: tensor-core, register-resident P ------------
#define QSTRH 72
#define VSTRH 280
#define HOFF_QH 0
#define HOFF_QL (HOFF_QH + 272 * QSTRH)
#define HOFF_KH (HOFF_QL + 272 * QSTRH)
#define HOFF_KL (HOFF_KH + 272 * QSTRH)
#define HOFF_VT (HOFF_KL + 272 * QSTRH)
#define HOFF_END (HOFF_VT + 64 * VSTRH)
#define ATTN_SMEM_BYTES (HOFF_END * 2 + 964 * 4)

__global__ void __launch_bounds__(256) attn_kernel(const float* __restrict__ qkv,
                                                   const float* __restrict__ table,
                                                   float* __restrict__ out)
{
    extern __shared__ __align__(16) __half smh[];
    __half* Qh = smh + HOFF_QH;
    __half* Ql = smh + HOFF_QL;
    __half* Kh = smh + HOFF_KH;
    __half* Kl = smh + HOFF_KL;
    __half* Vt = smh + HOFF_VT;
    float*  bsf = (float*)(smh + HOFF_END);

    int bh = blockIdx.x;
    int b = bh >> 4, h = bh & 15;
    int tid = threadIdx.x, lane = tid & 31, w = tid >> 5;
    const float* qg = qkv + (size_t)b * NTOK * STRQ + h * HD;
    const float* kg = qg + DMODEL;
    const float* vg = qg + 2 * DMODEL;

    for (int i = tid; i < 272 * 64; i += 256) {
        int r = i >> 6, c = i & 63;
        float qv = 0.f, kv = 0.f;
        if (r < NTOK) {
            qv = qg[(size_t)r * STRQ + c];
            kv = kg[(size_t)r * STRQ + c];
        }
        __half qh_ = __float2half_rn(qv);
        __half kh_ = __float2half_rn(kv);
        Qh[r * QSTRH + c] = qh_;
        Ql[r * QSTRH + c] = __float2half_rn(qv - __half2float(qh_));
        Kh[r * QSTRH + c] = kh_;
        Kl[r * QSTRH + c] = __float2half_rn(kv - __half2float(kh_));
    }
    for (int i = tid; i < 64 * 272; i += 256) {
        int d = i & 63, kk = i >> 6;
        float v = (kk < NTOK) ? vg[(size_t)kk * STRQ + d] : 0.f;
        Vt[d * VSTRH + kk] = __float2half_rn(v);
    }
    for (int i = tid; i < 964; i += 256) bsf[i] = table[(size_t)i * NHEAD + h];
    __syncthreads();

    uint32_t base = (uint32_t)__cvta_generic_to_shared(smh);
    int r0 = lane >> 2;
    int cb = (lane & 3) * 2;
    int g = lane >> 3;

    for (int t = w; t < 17; t += 8) {
        int m0 = t * 16;
        uint32_t qfh[4][4], qfl[4][4];
#pragma unroll
        for (int ks = 0; ks < 4; ks++) {
            uint32_t off = (uint32_t)((m0 + (lane & 15)) * QSTRH + ks * 16 + (lane >> 4) * 8) * 2;
            LDSM4(qfh[ks][0], qfh[ks][1], qfh[ks][2], qfh[ks][3], base + HOFF_QH * 2 + off);
            LDSM4(qfl[ks][0], qfl[ks][1], qfl[ks][2], qfl[ks][3], base + HOFF_QL * 2 + off);
        }

        float sacc[34][4];
#pragma unroll
        for (int nt = 0; nt < 34; nt++)
#pragma unroll
            for (int r = 0; r < 4; r++) sacc[nt][r] = 0.f;

#pragma unroll
        for (int np = 0; np < 17; np++) {
#pragma unroll
            for (int ks = 0; ks < 4; ks++) {
                uint32_t roff = (uint32_t)((np * 16 + (g >> 1) * 8 + (lane & 7)) * QSTRH
                                           + ks * 16 + (g & 1) * 8) * 2;
                uint32_t bh0, bh1, bh2, bh3, bl0, bl1, bl2, bl3;
                LDSM4(bh0, bh1, bh2, bh3, base + HOFF_KH * 2 + roff);
                LDSM4(bl0, bl1, bl2, bl3, base + HOFF_KL * 2 + roff);
                MMAF(sacc[2*np],   qfh[ks][0], qfh[ks][1], qfh[ks][2], qfh[ks][3], bh0, bh1);
                MMAF(sacc[2*np+1], qfh[ks][0], qfh[ks][1], qfh[ks][2], qfh[ks][3], bh2, bh3);
                MMAF(sacc[2*np],   qfl[ks][0], qfl[ks][1], qfl[ks][2], qfl[ks][3], bh0, bh1);
                MMAF(sacc[2*np+1], qfl[ks][0], qfl[ks][1], qfl[ks][2], qfl[ks][3], bh2, bh3);
                MMAF(sacc[2*np],   qfh[ks][0], qfh[ks][1], qfh[ks][2], qfh[ks][3], bl0, bl1);
                MMAF(sacc[2*np+1], qfh[ks][0], qfh[ks][1], qfh[ks][2], qfh[ks][3], bl2, bl3);
            }
        }

        int q0g = m0 + r0, q1g = q0g + 8;
        int q0e = (q0g < 256) ? q0g : 256;
        int q1e = (q1g < 256) ? q1g : 256;
        int Cq0 = (q0e >= 1) ? (((q0e - 1) >> 4) * 31 + ((q0e - 1) & 15) + 480) : 0;
        int Cq1 = (q1e >= 1) ? (((q1e - 1) >> 4) * 31 + ((q1e - 1) & 15) + 480) : 0;

#pragma unroll
        for (int nt = 0; nt < 34; nt++) {
#pragma unroll
            for (int r = 0; r < 4; r++) {
                int col = nt * 8 + cb + (r & 1);
                int qe = (r < 2) ? q0e : q1e;
                int Cq = (r < 2) ? Cq0 : Cq1;
                if (col >= NTOK) { sacc[nt][r] = -1e30f; }
                else {
                    int idx;
                    if (qe == 0)        idx = (col == 0) ? 963 : 961;
                    else if (col == 0)  idx = 962;
                    else                idx = Cq - (((col - 1) >> 4) * 31 + ((col - 1) & 15));
                    sacc[nt][r] += bsf[idx];
                }
            }
        }
        float mx0 = -1e30f, mx1 = -1e30f;
#pragma unroll
        for (int nt = 0; nt < 34; nt++) {
            mx0 = fmaxf(mx0, fmaxf(sacc[nt][0], sacc[nt][1]));
            mx1 = fmaxf(mx1, fmaxf(sacc[nt][2], sacc[nt][3]));
        }
        mx0 = fmaxf(mx0, __shfl_xor_sync(0xffffffffu, mx0, 1));
        mx0 = fmaxf(mx0, __shfl_xor_sync(0xffffffffu, mx0, 2));
        mx1 = fmaxf(mx1, __shfl_xor_sync(0xffffffffu, mx1, 1));
        mx1 = fmaxf(mx1, __shfl_xor_sync(0xffffffffu, mx1, 2));
        float sum0 = 0.f, sum1 = 0.f;
#pragma unroll
        for (int nt = 0; nt < 34; nt++) {
            sacc[nt][0] = __expf(sacc[nt][0] - mx0);
            sacc[nt][1] = __expf(sacc[nt][1] - mx0);
            sacc[nt][2] = __expf(sacc[nt][2] - mx1);
            sacc[nt][3] = __expf(sacc[nt][3] - mx1);
            sum0 += sacc[nt][0] + sacc[nt][1];
            sum1 += sacc[nt][2] + sacc[nt][3];
        }
        sum0 += __shfl_xor_sync(0xffffffffu, sum0, 1);
        sum0 += __shfl_xor_sync(0xffffffffu, sum0, 2);
        sum1 += __shfl_xor_sync(0xffffffffu, sum1, 1);
        sum1 += __shfl_xor_sync(0xffffffffu, sum1, 2);
        float inv0 = 1.f / sum0, inv1 = 1.f / sum1;
#pragma unroll
        for (int nt = 0; nt < 34; nt++) {
            sacc[nt][0] *= inv0; sacc[nt][1] *= inv0;
            sacc[nt][2] *= inv1; sacc[nt][3] *= inv1;
        }

        float oacc[8][4];
#pragma unroll
        for (int dt = 0; dt < 8; dt++)
#pragma unroll
            for (int r = 0; r < 4; r++) oacc[dt][r] = 0.f;

#pragma unroll
        for (int j = 0; j < 17; j++) {
            uint32_t pa0, pa1, pa2, pa3;
            { __half2 tt = __floats2half2_rn(sacc[2*j][0],   sacc[2*j][1]);   pa0 = *(uint32_t*)&tt; }
            { __half2 tt = __floats2half2_rn(sacc[2*j][2],   sacc[2*j][3]);   pa1 = *(uint32_t*)&tt; }
            { __half2 tt = __floats2half2_rn(sacc[2*j+1][0], sacc[2*j+1][1]); pa2 = *(uint32_t*)&tt; }
            { __half2 tt = __floats2half2_rn(sacc[2*j+1][2], sacc[2*j+1][3]); pa3 = *(uint32_t*)&tt; }
#pragma unroll
            for (int dp = 0; dp < 4; dp++) {
                uint32_t roff = (uint32_t)((dp * 16 + (g >> 1) * 8 + (lane & 7)) * VSTRH
                                           + j * 16 + (g & 1) * 8) * 2;
                uint32_t vb0, vb1, vb2, vb3;
                LDSM4(vb0, vb1, vb2, vb3, base + HOFF_VT * 2 + roff);
                MMAF(oacc[2*dp],   pa0, pa1, pa2, pa3, vb0, vb1);
                MMAF(oacc[2*dp+1], pa0, pa1, pa2, pa3, vb2, vb3);
            }
        }

#pragma unroll
        for (int dt = 0; dt < 8; dt++) {
            if (q0g < NTOK) {
                float2 o2; o2.x = oacc[dt][0]; o2.y = oacc[dt][1];
                *(float2*)&out[((size_t)b * NTOK + q0g) * DMODEL + h * HD + dt * 8 + cb] = o2;
            }
            if (q1g < NTOK) {
                float2 o2; o2.x = oacc[dt][2]; o2.y = oacc[dt][3];
                *(float2*)&out[((size_t)b * NTOK + q1g) * DMODEL + h * HD + dt * 8 + cb] = o2;
            }
        }
    }
}

// ---------------- launch -----------------------------------------------------
extern "C" void kernel_launch(void* const* d_in, const int* in_sizes, int n_in,
                              void* d_out, int out_size)
{
    const float* x        = (const float*)d_in[0];
    const float* rope_cos = (const float*)d_in[1];
    const float* rope_sin = (const float*)d_in[2];
    const float* q_w      = (const float*)d_in[3];
    const float* q_b      = (const float*)d_in[4];
    const float* k_w      = (const float*)d_in[5];
    const float* v_w      = (const float*)d_in[6];
    const float* v_b      = (const float*)d_in[7];
    const float* table    = (const float*)d_in[8];
    const float* in_g     = (const float*)d_in[9];
    const float* in_b     = (const float*)d_in[10];
    const float* proj_w   = (const float*)d_in[11];
    const float* proj_b   = (const float*)d_in[12];
    const float* n1g      = (const float*)d_in[13];
    const float* n1b      = (const float*)d_in[14];
    const float* n2g      = (const float*)d_in[15];
    const float* n2b      = (const float*)d_in[16];
    const float* w1       = (const float*)d_in[17];
    const float* w1b      = (const float*)d_in[18];
    const float* w2       = (const float*)d_in[19];
    const float* w2b      = (const float*)d_in[20];
    const float* fg       = (const float*)d_in[21];
    const float* fb       = (const float*)d_in[22];
    const float* w3       = (const float*)d_in[23];
    const float* w3b      = (const float*)d_in[24];
    float* out = (float*)d_out;

    float *qkv, *att, *x1, *h12, *qkvb, *w12b;
    __half *a16, *h16, *qkvw16, *pw16, *w1216, *w316;
    cudaGetSymbolAddress((void**)&qkv,    g_qkv);
    cudaGetSymbolAddress((void**)&att,    g_att);
    cudaGetSymbolAddress((void**)&x1,     g_x1);
    cudaGetSymbolAddress((void**)&h12,    g_h12);
    cudaGetSymbolAddress((void**)&a16,    g_a16);
    cudaGetSymbolAddress((void**)&h16,    g_h16);
    cudaGetSymbolAddress((void**)&qkvw16, g_qkvw16);
    cudaGetSymbolAddress((void**)&pw16,   g_pw16);
    cudaGetSymbolAddress((void**)&w1216,  g_w1216);
    cudaGetSymbolAddress((void**)&w316,   g_w316);
    cudaGetSymbolAddress((void**)&qkvb,   g_qkvb);
    cudaGetSymbolAddress((void**)&w12b,   g_w12b);

    cudaFuncSetAttribute(attn_kernel, cudaFuncAttributeMaxDynamicSharedMemorySize, ATTN_SMEM_BYTES);
    cudaFuncSetAttribute(tgemm<false>, cudaFuncAttributeMaxDynamicSharedMemorySize, SMEM_G);
    cudaFuncSetAttribute(tgemm<true>,  cudaFuncAttributeMaxDynamicSharedMemorySize, SMEM_G);

    dim3 blk(256);
    dim3 blk_g(128);
    dim3 gQKV(3 * DMODEL / 128, (T_TOK + 127) / 128);   // (24, 129)
    dim3 gP(DMODEL / 128,       (T_TOK + 127) / 128);   // (8, 129)
    dim3 gW12(2 * HDIM / 128,   (T_TOK + 127) / 128);   // (64, 129)

    const int n4_1M = DMODEL * DMODEL / 4;
    const int n4_4M = HDIM * DMODEL / 4;

    // #1: convert q/k/v/proj weights
    cvt4<<<dim3((n4_1M + 255) / 256, 4), blk>>>(
        q_w, qkvw16,
        k_w, qkvw16 + (size_t)DMODEL * DMODEL,
        v_w, qkvw16 + (size_t)2 * DMODEL * DMODEL,
        proj_w, pw16, n4_1M);
    // #2: pack biases
    pack_biases<<<(3 * DMODEL + 2 * HDIM + 255) / 256, blk>>>(q_b, v_b, w1b, w2b, qkvb, w12b);
    // #3: norm1 -> fp16
    ln16<DMODEL><<<T_TOK, blk>>>(x, n1g, n1b, a16);
    // #4: fused QKV projection
    tgemm<false><<<gQKV, blk_g, SMEM_G>>>(a16, qkvw16, qkvb, nullptr, qkv, T_TOK, 3 * DMODEL, DMODEL);
    // #5: RoPE + q scaling
    rope_kernel<<<T_TOK, blk>>>(qkv, rope_cos, rope_sin);
    // #6: attention (tensor cores)
    attn_kernel<<<BATCH * NHEAD, blk, ATTN_SMEM_BYTES>>>(qkv, table, att);
    // #7: convert FFN weights
    cvt4<<<dim3((n4_4M + 255) / 256, 3), blk>>>(
        w1, w1216,
        w2, w1216 + (size_t)HDIM * DMODEL,
        w3, w316,
        w3, w316, n4_4M);
    // #8: inner LN -> fp16
    ln16<DMODEL><<<T_TOK, blk>>>(att, in_g, in_b, a16);
    // #9: proj (+ residual with x) -> x1
    tgemm<true><<<gP, blk_g, SMEM_G>>>(a16, pw16, proj_b, x, x1, T_TOK, DMODEL, DMODEL);
    // #10: norm2 -> fp16
    ln16<DMODEL><<<T_TOK, blk>>>(x1, n2g, n2b, a16);
    // #11: fused FFN up projection (w1|w2)
    tgemm<false><<<gW12, blk_g, SMEM_G>>>(a16, w1216, w12b, nullptr, h12, T_TOK, 2 * HDIM, DMODEL);
    // #12: silu(x1h)*x2h -> ffn LN -> fp16
    silu_ln16<<<T_TOK, blk>>>(h12, fg, fb, h16);
    // #13: down projection + residual -> out
    tgemm<true><<<gP, blk_g, SMEM_G>>>(h16, w316, w3b, x1, out, T_TOK, DMODEL, HDIM);
}

// round 16
// speedup vs baseline: 1.5156x; 1.0030x over previous
#include <cuda_runtime.h>
#include <cuda_fp16.h>
#include <stdint.h>
#include <math.h>

#define NTOK   257
#define BATCH  64
#define T_TOK  (BATCH * NTOK)   // 16448
#define DMODEL 1024
#define NHEAD  16
#define HD     64
#define HDIM   4096
#define LN_EPS 1e-5f
#define STRQ   3072              // fused qkv row stride

// ---------------- scratch (device globals; no allocations allowed) ----------
__device__ __align__(16) float g_qkv[(size_t)T_TOK * STRQ];
__device__ __align__(16) float g_att[(size_t)T_TOK * DMODEL];
__device__ __align__(16) float g_x1 [(size_t)T_TOK * DMODEL];
__device__ __align__(16) float g_h12[(size_t)T_TOK * 2 * HDIM];

__device__ __align__(16) __half g_a16[(size_t)T_TOK * DMODEL];
__device__ __align__(16) __half g_h16[(size_t)T_TOK * HDIM];
__device__ __align__(16) __half g_qkvw16[(size_t)3 * DMODEL * DMODEL];
__device__ __align__(16) __half g_pw16[(size_t)DMODEL * DMODEL];
__device__ __align__(16) __half g_w1216[(size_t)2 * HDIM * DMODEL];
__device__ __align__(16) __half g_w316[(size_t)DMODEL * HDIM];
__device__ __align__(16) float  g_qkvb[3 * DMODEL];
__device__ __align__(16) float  g_w12b[2 * HDIM];

// ---------------- fp32 -> fp16 helpers --------------------------------------
__device__ __forceinline__ uint2 pack16(float4 t)
{
    __half2 a = __floats2half2_rn(t.x, t.y);
    __half2 b = __floats2half2_rn(t.z, t.w);
    uint2 r;
    r.x = *(uint32_t*)&a;
    r.y = *(uint32_t*)&b;
    return r;
}

__global__ void __launch_bounds__(256) cvt4(const float* __restrict__ s0, __half* __restrict__ d0,
                                            const float* __restrict__ s1, __half* __restrict__ d1,
                                            const float* __restrict__ s2, __half* __restrict__ d2,
                                            const float* __restrict__ s3, __half* __restrict__ d3,
                                            int n4)
{
    int i = blockIdx.x * 256 + threadIdx.x;
    if (i >= n4) return;
    const float* s = (blockIdx.y == 0) ? s0 : (blockIdx.y == 1) ? s1 : (blockIdx.y == 2) ? s2 : s3;
    __half*      d = (blockIdx.y == 0) ? d0 : (blockIdx.y == 1) ? d1 : (blockIdx.y == 2) ? d2 : d3;
    ((uint2*)d)[i] = pack16(((const float4*)s)[i]);
}

__global__ void __launch_bounds__(256) pack_biases(const float* __restrict__ qb,
                                                   const float* __restrict__ vb,
                                                   const float* __restrict__ b1,
                                                   const float* __restrict__ b2,
                                                   float* __restrict__ qkvb,
                                                   float* __restrict__ w12b)
{
    int i = blockIdx.x * 256 + threadIdx.x;
    if (i < 3 * DMODEL) {
        qkvb[i] = (i < DMODEL) ? qb[i] : ((i < 2 * DMODEL) ? 0.f : vb[i - 2 * DMODEL]);
    } else {
        int j = i - 3 * DMODEL;
        if (j < 2 * HDIM) w12b[j] = (j < HDIM) ? b1[j] : b2[j - HDIM];
    }
}

// ---------------- mma.sync GEMM v4 ------------------------------------------
// CTA tile 128x128, 4 warps (2x2), warp tile 64x64, 128 threads.
// Pair-buffered: 4 stages, chunks consumed in pairs {2p,2p+1} on stages
// {0,1}/{2,3} while the next pair loads into the other two stages.
// One wait_group 0 + one __syncthreads per TWO K-chunks. 2 CTAs/SM.
#define RSB    80
#define APLANE (128 * RSB)
#define BPLANE (128 * RSB)
#define STAGE  (APLANE + BPLANE)
#define NSTAGE 4
#define SMEM_G (NSTAGE * STAGE)   // 81920

#define LDSM4(r0, r1, r2, r3, addr) \
    asm volatile("ldmatrix.sync.aligned.m8n8.x4.shared.b16 {%0,%1,%2,%3}, [%4];" \
                 : "=r"(r0), "=r"(r1), "=r"(r2), "=r"(r3) : "r"(addr))

#define MMA16816(c, a, b) \
    asm volatile("mma.sync.aligned.m16n8k16.row.col.f32.f16.f16.f32 " \
                 "{%0,%1,%2,%3}, {%4,%5,%6,%7}, {%8,%9}, {%0,%1,%2,%3};" \
                 : "+f"((c)[0]), "+f"((c)[1]), "+f"((c)[2]), "+f"((c)[3]) \
                 : "r"((a)[0]), "r"((a)[1]), "r"((a)[2]), "r"((a)[3]), \
                   "r"((b)[0]), "r"((b)[1]))

#define MMAF(c, a0_, a1_, a2_, a3_, b0_, b1_) \
    asm volatile("mma.sync.aligned.m16n8k16.row.col.f32.f16.f16.f32 " \
                 "{%0,%1,%2,%3}, {%4,%5,%6,%7}, {%8,%9}, {%0,%1,%2,%3};" \
                 : "+f"((c)[0]), "+f"((c)[1]), "+f"((c)[2]), "+f"((c)[3]) \
                 : "r"(a0_), "r"(a1_), "r"(a2_), "r"(a3_), "r"(b0_), "r"(b1_))

template<bool RES>
__global__ void __launch_bounds__(128, 2) tgemm(const __half* __restrict__ A,
                                                const __half* __restrict__ B,
                                                const float* __restrict__ bias,
                                                const float* __restrict__ res,
                                                float* __restrict__ C,
                                                int M, int N, int K)
{
    extern __shared__ __align__(16) char dsm[];
    uint32_t sb = (uint32_t)__cvta_generic_to_shared(dsm);

    int tid = threadIdx.x, lane = tid & 31, warp = tid >> 5;
    int wm = warp >> 1, wn = warp & 1;           // warp grid 2 x 2
    int m0 = blockIdx.y * 128, n0 = blockIdx.x * 128;

    float acc[4][8][4];
#pragma unroll
    for (int i = 0; i < 4; i++)
#pragma unroll
        for (int j = 0; j < 8; j++)
#pragma unroll
            for (int r = 0; r < 4; r++) acc[i][j][r] = 0.f;

    auto issue_loads = [&](int c) {
        int k0 = c * 32;
        uint32_t sbuf = sb + (uint32_t)(c & (NSTAGE - 1)) * STAGE;
#pragma unroll
        for (int i = 0; i < 8; i++) {
            int gi = i * 128 + tid;       // 0..1023
            int p = gi >> 9;              // 0:A 1:B
            int idx = gi & 511;
            int row = idx >> 2, cc = idx & 3;
            if (p == 0) {
                int grow = m0 + row;
                int sz = 16;
                if (grow >= M) { grow = 0; sz = 0; }
                const void* src = A + (size_t)grow * K + k0 + cc * 8;
                uint32_t dst = sbuf + (uint32_t)(row * RSB + cc * 16);
                asm volatile("cp.async.ca.shared.global [%0], [%1], 16, %2;"
                             :: "r"(dst), "l"(src), "r"(sz));
            } else {
                const void* src = B + (size_t)(n0 + row) * K + k0 + cc * 8;
                uint32_t dst = sbuf + APLANE + (uint32_t)(row * RSB + cc * 16);
                asm volatile("cp.async.cg.shared.global [%0], [%1], 16;"
                             :: "r"(dst), "l"(src));
            }
        }
        asm volatile("cp.async.commit_group;" ::: "memory");
    };

    int KT = K >> 5;   // even for K in {1024, 4096}
    issue_loads(0);
    issue_loads(1);
    asm volatile("cp.async.wait_group 0;" ::: "memory");
    __syncthreads();

    for (int c = 0; c < KT; c += 2) {
        if (c + 2 < KT) {                  // prefetch next pair into other stages
            issue_loads(c + 2);
            issue_loads(c + 3);
        }

#pragma unroll
        for (int hc = 0; hc < 2; hc++) {
            uint32_t sbuf = sb + (uint32_t)((c + hc) & (NSTAGE - 1)) * STAGE;
#pragma unroll
            for (int kk = 0; kk < 32; kk += 16) {
                uint32_t af[4][4], bf[8][2];
#pragma unroll
                for (int mi = 0; mi < 4; mi++) {
                    int arow = wm * 64 + mi * 16 + (lane & 15);
                    uint32_t aoff = (uint32_t)(arow * RSB + (kk + (lane >> 4) * 8) * 2);
                    LDSM4(af[mi][0], af[mi][1], af[mi][2], af[mi][3], sbuf + aoff);
                }
#pragma unroll
                for (int nj = 0; nj < 4; nj++) {
                    int g = lane >> 3;
                    int nrow = wn * 64 + nj * 16 + (g >> 1) * 8 + (lane & 7);
                    uint32_t boff = (uint32_t)(nrow * RSB + (kk + (g & 1) * 8) * 2);
                    LDSM4(bf[nj*2][0], bf[nj*2][1], bf[nj*2+1][0], bf[nj*2+1][1],
                          sbuf + APLANE + boff);
                }
#pragma unroll
                for (int mi = 0; mi < 4; mi++)
#pragma unroll
                    for (int ni = 0; ni < 8; ni++)
                        MMA16816(acc[mi][ni], af[mi], bf[ni]);
            }
        }

        if (c + 2 < KT) {
            asm volatile("cp.async.wait_group 0;" ::: "memory");
            __syncthreads();
        }
    }

    // epilogue
#pragma unroll
    for (int mi = 0; mi < 4; mi++) {
#pragma unroll
        for (int ni = 0; ni < 8; ni++) {
            int r0 = m0 + wm * 64 + mi * 16 + (lane >> 2);
            int col = n0 + wn * 64 + ni * 8 + (lane & 3) * 2;
            float bx = 0.f, by = 0.f;
            if (bias) { bx = bias[col]; by = bias[col + 1]; }
            float2 v0, v1;
            v0.x = acc[mi][ni][0] + bx; v0.y = acc[mi][ni][1] + by;
            v1.x = acc[mi][ni][2] + bx; v1.y = acc[mi][ni][3] + by;
            if (r0 < M) {
                size_t off = (size_t)r0 * N + col;
                if (RES) { float2 rr = *(const float2*)&res[off]; v0.x += rr.x; v0.y += rr.y; }
                *(float2*)&C[off] = v0;
            }
            if (r0 + 8 < M) {
                size_t off = (size_t)(r0 + 8) * N + col;
                if (RES) { float2 rr = *(const float2*)&res[off]; v1.x += rr.x; v1.y += rr.y; }
                *(float2*)&C[off] = v1;
            }
        }
    }
}

// ---------------- LayerNorm -> fp16 plane ------------------------------------
template<int W>
__global__ void __launch_bounds__(256) ln16(const float* __restrict__ x,
                                            const float* __restrict__ g,
                                            const float* __restrict__ b,
                                            __half* __restrict__ o16)
{
    constexpr int V = W / 1024;
    __shared__ float red0[8], red1[8];
    __shared__ float stats[2];
    size_t rb = (size_t)blockIdx.x * W;
    const float4* xr = (const float4*)(x + rb);
    float4 vv[V];
    float s = 0.f, s2 = 0.f;
#pragma unroll
    for (int i = 0; i < V; i++) {
        float4 t = xr[threadIdx.x + i * 256];
        vv[i] = t;
        s  += t.x + t.y + t.z + t.w;
        s2 += t.x*t.x + t.y*t.y + t.z*t.z + t.w*t.w;
    }
#pragma unroll
    for (int o = 16; o; o >>= 1) {
        s  += __shfl_xor_sync(0xffffffffu, s,  o);
        s2 += __shfl_xor_sync(0xffffffffu, s2, o);
    }
    if ((threadIdx.x & 31) == 0) { red0[threadIdx.x >> 5] = s; red1[threadIdx.x >> 5] = s2; }
    __syncthreads();
    if (threadIdx.x == 0) {
        float a = 0.f, c = 0.f;
#pragma unroll
        for (int i = 0; i < 8; i++) { a += red0[i]; c += red1[i]; }
        float mu  = a / (float)W;
        float var = c / (float)W - mu * mu;
        stats[0] = mu;
        stats[1] = rsqrtf(var + LN_EPS);
    }
    __syncthreads();
    float mu = stats[0], inv = stats[1];
    const float4* g4 = (const float4*)g;
    const float4* b4 = (const float4*)b;
#pragma unroll
    for (int i = 0; i < V; i++) {
        int c = threadIdx.x + i * 256;
        float4 gg = g4[c], bb = b4[c], t = vv[i], o;
        o.x = (t.x - mu) * inv * gg.x + bb.x;
        o.y = (t.y - mu) * inv * gg.y + bb.y;
        o.z = (t.z - mu) * inv * gg.z + bb.z;
        o.w = (t.w - mu) * inv * gg.w + bb.w;
        ((uint2*)(o16 + rb))[c] = pack16(o);
    }
}

// ---------------- fused SiLU(x1)*x2 -> LayerNorm -> fp16 ---------------------
__global__ void __launch_bounds__(256) silu_ln16(const float* __restrict__ h12,
                                                 const float* __restrict__ g,
                                                 const float* __restrict__ b,
                                                 __half* __restrict__ o16)
{
    constexpr int W = HDIM;
    constexpr int V = W / 1024;
    __shared__ float red0[8], red1[8];
    __shared__ float stats[2];
    size_t rb12 = (size_t)blockIdx.x * (2 * HDIM);
    size_t rb   = (size_t)blockIdx.x * W;
    const float4* ar = (const float4*)(h12 + rb12);
    const float4* cr = (const float4*)(h12 + rb12 + HDIM);
    float4 vv[V];
    float s = 0.f, s2 = 0.f;
#pragma unroll
    for (int i = 0; i < V; i++) {
        float4 a = ar[threadIdx.x + i * 256];
        float4 c = cr[threadIdx.x + i * 256];
        float4 t;
        t.x = a.x / (1.f + __expf(-a.x)) * c.x;
        t.y = a.y / (1.f + __expf(-a.y)) * c.y;
        t.z = a.z / (1.f + __expf(-a.z)) * c.z;
        t.w = a.w / (1.f + __expf(-a.w)) * c.w;
        vv[i] = t;
        s  += t.x + t.y + t.z + t.w;
        s2 += t.x*t.x + t.y*t.y + t.z*t.z + t.w*t.w;
    }
#pragma unroll
    for (int o = 16; o; o >>= 1) {
        s  += __shfl_xor_sync(0xffffffffu, s,  o);
        s2 += __shfl_xor_sync(0xffffffffu, s2, o);
    }
    if ((threadIdx.x & 31) == 0) { red0[threadIdx.x >> 5] = s; red1[threadIdx.x >> 5] = s2; }
    __syncthreads();
    if (threadIdx.x == 0) {
        float a = 0.f, c = 0.f;
#pragma unroll
        for (int i = 0; i < 8; i++) { a += red0[i]; c += red1[i]; }
        float mu  = a / (float)W;
        float var = c / (float)W - mu * mu;
        stats[0] = mu;
        stats[1] = rsqrtf(var + LN_EPS);
    }
    __syncthreads();
    float mu = stats[0], inv = stats[1];
    const float4* g4 = (const float4*)g;
    const float4* b4 = (const float4*)b;
#pragma unroll
    for (int i = 0; i < V; i++) {
        int c = threadIdx.x + i * 256;
        float4 gg = g4[c], bb = b4[c], t = vv[i], o;
        o.x = (t.x - mu) * inv * gg.x + bb.x;
        o.y = (t.y - mu) * inv * gg.y + bb.y;
        o.z = (t.z - mu) * inv * gg.z + bb.z;
        o.w = (t.w - mu) * inv * gg.w + bb.w;
        ((uint2*)(o16 + rb))[c] = pack16(o);
    }
}

// ---------------- RoPE on q,k in fused qkv buffer; scale q ------------------
__global__ void __launch_bounds__(256) rope_kernel(float* __restrict__ qkv,
                                                   const float* __restrict__ cosb,
                                                   const float* __restrict__ sinb)
{
    const float scale = 0.125f;
    int row = blockIdx.x;
    int n = row % NTOK;
    float4* qr = (float4*)(qkv + (size_t)row * STRQ);
    float4* kr = (float4*)(qkv + (size_t)row * STRQ + DMODEL);
    int ci = threadIdx.x;
    if (n == 0) {
        float4 t = qr[ci];
        t.x *= scale; t.y *= scale; t.z *= scale; t.w *= scale;
        qr[ci] = t;
        return;
    }
    int d = (ci * 4) & 63;
    const float4 cs = *(const float4*)(cosb + (size_t)(n - 1) * HD + d);
    const float4 sn = *(const float4*)(sinb + (size_t)(n - 1) * HD + d);
    float4 t = qr[ci], o;
    o.x = t.x * cs.x - t.y * sn.x;
    o.y = t.y * cs.y + t.x * sn.y;
    o.z = t.z * cs.z - t.w * sn.z;
    o.w = t.w * cs.w + t.z * sn.w;
    o.x *= scale; o.y *= scale; o.z *= scale; o.w *= scale;
    qr[ci] = o;
    t = kr[ci];
    o.x = t.x * cs.x - t.y * sn.x;
    o.y = t.y * cs.y + t.x * sn.y;
    o.z = t.z * cs.z - t.w * sn.z;
    o.w = t.w * cs.w + t.z * sn.w;
    kr[ci] = o;
}

// ---------------- attention v4: tensor-core, register-resident P ------------
#define QSTRH 72
#define VSTRH 280
#define HOFF_QH 0
#define HOFF_QL (HOFF_QH + 272 * QSTRH)
#define HOFF_KH (HOFF_QL + 272 * QSTRH)
#define HOFF_KL (HOFF_KH + 272 * QSTRH)
#define HOFF_VT (HOFF_KL + 272 * QSTRH)
#define HOFF_END (HOFF_VT + 64 * VSTRH)
#define ATTN_SMEM_BYTES (HOFF_END * 2 + 964 * 4)

__global__ void __launch_bounds__(256) attn_kernel(const float* __restrict__ qkv,
                                                   const float* __restrict__ table,
                                                   float* __restrict__ out)
{
    extern __shared__ __align__(16) __half smh[];
    __half* Qh = smh + HOFF_QH;
    __half* Ql = smh + HOFF_QL;
    __half* Kh = smh + HOFF_KH;
    __half* Kl = smh + HOFF_KL;
    __half* Vt = smh + HOFF_VT;
    float*  bsf = (float*)(smh + HOFF_END);

    int bh = blockIdx.x;
    int b = bh >> 4, h = bh & 15;
    int tid = threadIdx.x, lane = tid & 31, w = tid >> 5;
    const float* qg = qkv + (size_t)b * NTOK * STRQ + h * HD;
    const float* kg = qg + DMODEL;
    const float* vg = qg + 2 * DMODEL;

    for (int i = tid; i < 272 * 64; i += 256) {
        int r = i >> 6, c = i & 63;
        float qv = 0.f, kv = 0.f;
        if (r < NTOK) {
            qv = qg[(size_t)r * STRQ + c];
            kv = kg[(size_t)r * STRQ + c];
        }
        __half qh_ = __float2half_rn(qv);
        __half kh_ = __float2half_rn(kv);
        Qh[r * QSTRH + c] = qh_;
        Ql[r * QSTRH + c] = __float2half_rn(qv - __half2float(qh_));
        Kh[r * QSTRH + c] = kh_;
        Kl[r * QSTRH + c] = __float2half_rn(kv - __half2float(kh_));
    }
    for (int i = tid; i < 64 * 272; i += 256) {
        int d = i & 63, kk = i >> 6;
        float v = (kk < NTOK) ? vg[(size_t)kk * STRQ + d] : 0.f;
        Vt[d * VSTRH + kk] = __float2half_rn(v);
    }
    for (int i = tid; i < 964; i += 256) bsf[i] = table[(size_t)i * NHEAD + h];
    __syncthreads();

    uint32_t base = (uint32_t)__cvta_generic_to_shared(smh);
    int r0 = lane >> 2;
    int cb = (lane & 3) * 2;
    int g = lane >> 3;

    for (int t = w; t < 17; t += 8) {
        int m0 = t * 16;
        uint32_t qfh[4][4], qfl[4][4];
#pragma unroll
        for (int ks = 0; ks < 4; ks++) {
            uint32_t off = (uint32_t)((m0 + (lane & 15)) * QSTRH + ks * 16 + (lane >> 4) * 8) * 2;
            LDSM4(qfh[ks][0], qfh[ks][1], qfh[ks][2], qfh[ks][3], base + HOFF_QH * 2 + off);
            LDSM4(qfl[ks][0], qfl[ks][1], qfl[ks][2], qfl[ks][3], base + HOFF_QL * 2 + off);
        }

        float sacc[34][4];
#pragma unroll
        for (int nt = 0; nt < 34; nt++)
#pragma unroll
            for (int r = 0; r < 4; r++) sacc[nt][r] = 0.f;

#pragma unroll
        for (int np = 0; np < 17; np++) {
#pragma unroll
            for (int ks = 0; ks < 4; ks++) {
                uint32_t roff = (uint32_t)((np * 16 + (g >> 1) * 8 + (lane & 7)) * QSTRH
                                           + ks * 16 + (g & 1) * 8) * 2;
                uint32_t bh0, bh1, bh2, bh3, bl0, bl1, bl2, bl3;
                LDSM4(bh0, bh1, bh2, bh3, base + HOFF_KH * 2 + roff);
                LDSM4(bl0, bl1, bl2, bl3, base + HOFF_KL * 2 + roff);
                MMAF(sacc[2*np],   qfh[ks][0], qfh[ks][1], qfh[ks][2], qfh[ks][3], bh0, bh1);
                MMAF(sacc[2*np+1], qfh[ks][0], qfh[ks][1], qfh[ks][2], qfh[ks][3], bh2, bh3);
                MMAF(sacc[2*np],   qfl[ks][0], qfl[ks][1], qfl[ks][2], qfl[ks][3], bh0, bh1);
                MMAF(sacc[2*np+1], qfl[ks][0], qfl[ks][1], qfl[ks][2], qfl[ks][3], bh2, bh3);
                MMAF(sacc[2*np],   qfh[ks][0], qfh[ks][1], qfh[ks][2], qfh[ks][3], bl0, bl1);
                MMAF(sacc[2*np+1], qfh[ks][0], qfh[ks][1], qfh[ks][2], qfh[ks][3], bl2, bl3);
            }
        }

        int q0g = m0 + r0, q1g = q0g + 8;
        int q0e = (q0g < 256) ? q0g : 256;
        int q1e = (q1g < 256) ? q1g : 256;
        int Cq0 = (q0e >= 1) ? (((q0e - 1) >> 4) * 31 + ((q0e - 1) & 15) + 480) : 0;
        int Cq1 = (q1e >= 1) ? (((q1e - 1) >> 4) * 31 + ((q1e - 1) & 15) + 480) : 0;

#pragma unroll
        for (int nt = 0; nt < 34; nt++) {
#pragma unroll
            for (int r = 0; r < 4; r++) {
                int col = nt * 8 + cb + (r & 1);
                int qe = (r < 2) ? q0e : q1e;
                int Cq = (r < 2) ? Cq0 : Cq1;
                if (col >= NTOK) { sacc[nt][r] = -1e30f; }
                else {
                    int idx;
                    if (qe == 0)        idx = (col == 0) ? 963 : 961;
                    else if (col == 0)  idx = 962;
                    else                idx = Cq - (((col - 1) >> 4) * 31 + ((col - 1) & 15));
                    sacc[nt][r] += bsf[idx];
                }
            }
        }
        float mx0 = -1e30f, mx1 = -1e30f;
#pragma unroll
        for (int nt = 0; nt < 34; nt++) {
            mx0 = fmaxf(mx0, fmaxf(sacc[nt][0], sacc[nt][1]));
            mx1 = fmaxf(mx1, fmaxf(sacc[nt][2], sacc[nt][3]));
        }
        mx0 = fmaxf(mx0, __shfl_xor_sync(0xffffffffu, mx0, 1));
        mx0 = fmaxf(mx0, __shfl_xor_sync(0xffffffffu, mx0, 2));
        mx1 = fmaxf(mx1, __shfl_xor_sync(0xffffffffu, mx1, 1));
        mx1 = fmaxf(mx1, __shfl_xor_sync(0xffffffffu, mx1, 2));
        float sum0 = 0.f, sum1 = 0.f;
#pragma unroll
        for (int nt = 0; nt < 34; nt++) {
            sacc[nt][0] = __expf(sacc[nt][0] - mx0);
            sacc[nt][1] = __expf(sacc[nt][1] - mx0);
            sacc[nt][2] = __expf(sacc[nt][2] - mx1);
            sacc[nt][3] = __expf(sacc[nt][3] - mx1);
            sum0 += sacc[nt][0] + sacc[nt][1];
            sum1 += sacc[nt][2] + sacc[nt][3];
        }
        sum0 += __shfl_xor_sync(0xffffffffu, sum0, 1);
        sum0 += __shfl_xor_sync(0xffffffffu, sum0, 2);
        sum1 += __shfl_xor_sync(0xffffffffu, sum1, 1);
        sum1 += __shfl_xor_sync(0xffffffffu, sum1, 2);
        float inv0 = 1.f / sum0, inv1 = 1.f / sum1;
#pragma unroll
        for (int nt = 0; nt < 34; nt++) {
            sacc[nt][0] *= inv0; sacc[nt][1] *= inv0;
            sacc[nt][2] *= inv1; sacc[nt][3] *= inv1;
        }

        float oacc[8][4];
#pragma unroll
        for (int dt = 0; dt < 8; dt++)
#pragma unroll
            for (int r = 0; r < 4; r++) oacc[dt][r] = 0.f;

#pragma unroll
        for (int j = 0; j < 17; j++) {
            uint32_t pa0, pa1, pa2, pa3;
            { __half2 tt = __floats2half2_rn(sacc[2*j][0],   sacc[2*j][1]);   pa0 = *(uint32_t*)&tt; }
            { __half2 tt = __floats2half2_rn(sacc[2*j][2],   sacc[2*j][3]);   pa1 = *(uint32_t*)&tt; }
            { __half2 tt = __floats2half2_rn(sacc[2*j+1][0], sacc[2*j+1][1]); pa2 = *(uint32_t*)&tt; }
            { __half2 tt = __floats2half2_rn(sacc[2*j+1][2], sacc[2*j+1][3]); pa3 = *(uint32_t*)&tt; }
#pragma unroll
            for (int dp = 0; dp < 4; dp++) {
                uint32_t roff = (uint32_t)((dp * 16 + (g >> 1) * 8 + (lane & 7)) * VSTRH
                                           + j * 16 + (g & 1) * 8) * 2;
                uint32_t vb0, vb1, vb2, vb3;
                LDSM4(vb0, vb1, vb2, vb3, base + HOFF_VT * 2 + roff);
                MMAF(oacc[2*dp],   pa0, pa1, pa2, pa3, vb0, vb1);
                MMAF(oacc[2*dp+1], pa0, pa1, pa2, pa3, vb2, vb3);
            }
        }

#pragma unroll
        for (int dt = 0; dt < 8; dt++) {
            if (q0g < NTOK) {
                float2 o2; o2.x = oacc[dt][0]; o2.y = oacc[dt][1];
                *(float2*)&out[((size_t)b * NTOK + q0g) * DMODEL + h * HD + dt * 8 + cb] = o2;
            }
            if (q1g < NTOK) {
                float2 o2; o2.x = oacc[dt][2]; o2.y = oacc[dt][3];
                *(float2*)&out[((size_t)b * NTOK + q1g) * DMODEL + h * HD + dt * 8 + cb] = o2;
            }
        }
    }
}

// ---------------- launch -----------------------------------------------------
extern "C" void kernel_launch(void* const* d_in, const int* in_sizes, int n_in,
                              void* d_out, int out_size)
{
    const float* x        = (const float*)d_in[0];
    const float* rope_cos = (const float*)d_in[1];
    const float* rope_sin = (const float*)d_in[2];
    const float* q_w      = (const float*)d_in[3];
    const float* q_b      = (const float*)d_in[4];
    const float* k_w      = (const float*)d_in[5];
    const float* v_w      = (const float*)d_in[6];
    const float* v_b      = (const float*)d_in[7];
    const float* table    = (const float*)d_in[8];
    const float* in_g     = (const float*)d_in[9];
    const float* in_b     = (const float*)d_in[10];
    const float* proj_w   = (const float*)d_in[11];
    const float* proj_b   = (const float*)d_in[12];
    const float* n1g      = (const float*)d_in[13];
    const float* n1b      = (const float*)d_in[14];
    const float* n2g      = (const float*)d_in[15];
    const float* n2b      = (const float*)d_in[16];
    const float* w1       = (const float*)d_in[17];
    const float* w1b      = (const float*)d_in[18];
    const float* w2       = (const float*)d_in[19];
    const float* w2b      = (const float*)d_in[20];
    const float* fg       = (const float*)d_in[21];
    const float* fb       = (const float*)d_in[22];
    const float* w3       = (const float*)d_in[23];
    const float* w3b      = (const float*)d_in[24];
    float* out = (float*)d_out;

    float *qkv, *att, *x1, *h12, *qkvb, *w12b;
    __half *a16, *h16, *qkvw16, *pw16, *w1216, *w316;
    cudaGetSymbolAddress((void**)&qkv,    g_qkv);
    cudaGetSymbolAddress((void**)&att,    g_att);
    cudaGetSymbolAddress((void**)&x1,     g_x1);
    cudaGetSymbolAddress((void**)&h12,    g_h12);
    cudaGetSymbolAddress((void**)&a16,    g_a16);
    cudaGetSymbolAddress((void**)&h16,    g_h16);
    cudaGetSymbolAddress((void**)&qkvw16, g_qkvw16);
    cudaGetSymbolAddress((void**)&pw16,   g_pw16);
    cudaGetSymbolAddress((void**)&w1216,  g_w1216);
    cudaGetSymbolAddress((void**)&w316,   g_w316);
    cudaGetSymbolAddress((void**)&qkvb,   g_qkvb);
    cudaGetSymbolAddress((void**)&w12b,   g_w12b);

    cudaFuncSetAttribute(attn_kernel, cudaFuncAttributeMaxDynamicSharedMemorySize, ATTN_SMEM_BYTES);
    cudaFuncSetAttribute(tgemm<false>, cudaFuncAttributeMaxDynamicSharedMemorySize, SMEM_G);
    cudaFuncSetAttribute(tgemm<true>,  cudaFuncAttributeMaxDynamicSharedMemorySize, SMEM_G);

    dim3 blk(256);
    dim3 blk_g(128);
    dim3 gQKV(3 * DMODEL / 128, (T_TOK + 127) / 128);   // (24, 129)
    dim3 gP(DMODEL / 128,       (T_TOK + 127) / 128);   // (8, 129)
    dim3 gW12(2 * HDIM / 128,   (T_TOK + 127) / 128);   // (64, 129)

    const int n4_1M = DMODEL * DMODEL / 4;
    const int n4_4M = HDIM * DMODEL / 4;

    // #1: convert q/k/v/proj weights
    cvt4<<<dim3((n4_1M + 255) / 256, 4), blk>>>(
        q_w, qkvw16,
        k_w, qkvw16 + (size_t)DMODEL * DMODEL,
        v_w, qkvw16 + (size_t)2 * DMODEL * DMODEL,
        proj_w, pw16, n4_1M);
    // #2: pack biases
    pack_biases<<<(3 * DMODEL + 2 * HDIM + 255) / 256, blk>>>(q_b, v_b, w1b, w2b, qkvb, w12b);
    // #3: norm1 -> fp16
    ln16<DMODEL><<<T_TOK, blk>>>(x, n1g, n1b, a16);
    // #4: fused QKV projection
    tgemm<false><<<gQKV, blk_g, SMEM_G>>>(a16, qkvw16, qkvb, nullptr, qkv, T_TOK, 3 * DMODEL, DMODEL);
    // #5: RoPE + q scaling
    rope_kernel<<<T_TOK, blk>>>(qkv, rope_cos, rope_sin);
    // #6: attention (tensor cores)
    attn_kernel<<<BATCH * NHEAD, blk, ATTN_SMEM_BYTES>>>(qkv, table, att);
    // #7: convert FFN weights
    cvt4<<<dim3((n4_4M + 255) / 256, 3), blk>>>(
        w1, w1216,
        w2, w1216 + (size_t)HDIM * DMODEL,
        w3, w316,
        w3, w316, n4_4M);
    // #8: inner LN -> fp16
    ln16<DMODEL><<<T_TOK, blk>>>(att, in_g, in_b, a16);
    // #9: proj (+ residual with x) -> x1
    tgemm<true><<<gP, blk_g, SMEM_G>>>(a16, pw16, proj_b, x, x1, T_TOK, DMODEL, DMODEL);
    // #10: norm2 -> fp16
    ln16<DMODEL><<<T_TOK, blk>>>(x1, n2g, n2b, a16);
    // #11: fused FFN up projection (w1|w2)
    tgemm<false><<<gW12, blk_g, SMEM_G>>>(a16, w1216, w12b, nullptr, h12, T_TOK, 2 * HDIM, DMODEL);
    // #12: silu(x1h)*x2h -> ffn LN -> fp16
    silu_ln16<<<T_TOK, blk>>>(h12, fg, fb, h16);
    // #13: down projection + residual -> out
    tgemm<true><<<gP, blk_g, SMEM_G>>>(h16, w316, w3b, x1, out, T_TOK, DMODEL, HDIM);
}